// round 2
// baseline (speedup 1.0000x reference)
#include <cuda_runtime.h>
#include <cstdint>
#include <cstdio>

#define BB 128     // batch
#define HH 1024    // hidden
#define FF 128     // features
#define NS 96      // samples
#define NPRED 8    // horizon
#define HS_SLOT (BB*HH)     // 131072
#define PRED_SLOT (BB*FF)   // 16384

// ---------------- device scratch (static: no allocations allowed) ----------------
__device__ float g_hs0[2][NS*HS_SLOT];   // layer0 h, double buffered across inner steps
__device__ float g_hs1[2][NS*HS_SLOT];   // layer1 h
__device__ float g_cs0[NS*HS_SLOT];      // layer0 c (in-place safe)
__device__ float g_cs1[NS*HS_SLOT];      // layer1 c
__device__ float g_preds[NPRED][NS*PRED_SLOT];

// ---------------- tf32 helpers ----------------
__device__ __forceinline__ uint32_t f2tf(float x) {
    uint32_t r;
    asm("cvt.rna.tf32.f32 %0, %1;" : "=r"(r) : "f"(x));
    return r;
}

__device__ __forceinline__ void mma8(float* c, uint32_t a0, uint32_t a1, uint32_t a2,
                                     uint32_t a3, uint32_t b0, uint32_t b1) {
    asm volatile(
        "mma.sync.aligned.m16n8k8.row.col.f32.tf32.tf32.f32 "
        "{%0,%1,%2,%3},{%4,%5,%6,%7},{%8,%9},{%0,%1,%2,%3};\n"
        : "+f"(c[0]), "+f"(c[1]), "+f"(c[2]), "+f"(c[3])
        : "r"(a0), "r"(a1), "r"(a2), "r"(a3), "r"(b0), "r"(b1));
}

// ---------------- fused LSTM cell ----------------
// Computes G = Ax @ Wih^T + Ah @ Whh^T (+ biases), gate nonlinearities, c/h update.
// Tile: BM=128 rows x BN=64 gate-cols (= 16 hidden units x 4 gates). 256 threads.
// grid.x = 1024/16 = 64 (hidden-unit blocks), grid.y = rows/128.
__global__ __launch_bounds__(256) void lstm_cell(
    const float* __restrict__ Ax, int Kx,
    const float* __restrict__ Ah,
    const float* __restrict__ Wih,   // [4096, Kx]
    const float* __restrict__ Whh,   // [4096, 1024]
    const float* __restrict__ bih, const float* __restrict__ bhh,
    const float* __restrict__ cprev,
    float* __restrict__ hout, float* __restrict__ cout)
{
    __shared__ float sm[128 * 65];              // 8320 floats; overlays tiles + gate buffer
    float* sA = sm;                              // 128 x 36 (padded)
    float* sB = sm + 128 * 36;                   // 64 x 36

    const int tid  = threadIdx.x;
    const int warp = tid >> 5, lane = tid & 31;
    const int gid  = lane >> 2, tig = lane & 3;
    const int wm   = (warp & 3) * 32;            // 4 warps along M
    const int wn   = (warp >> 2) * 32;           // 2 warps along N
    const int j0   = blockIdx.x * 16;            // hidden-unit block
    const size_t rowbase = (size_t)blockIdx.y * 128;

    float acc[2][4][4];
    #pragma unroll
    for (int i = 0; i < 2; i++)
        #pragma unroll
        for (int j = 0; j < 4; j++)
            #pragma unroll
            for (int q = 0; q < 4; q++) acc[i][j][q] = 0.f;

    for (int phase = 0; phase < 2; phase++) {
        const float* A = phase ? Ah  : Ax;
        const float* W = phase ? Whh : Wih;
        const int K = phase ? HH : Kx;
        for (int k0 = 0; k0 < K; k0 += 32) {
            // A tile 128x32
            #pragma unroll
            for (int i = 0; i < 4; i++) {
                int q = tid + i * 256;
                int r = q >> 3, c4 = (q & 7) << 2;
                const float4 v = *(const float4*)(A + (rowbase + r) * (size_t)K + k0 + c4);
                float* d = sA + r * 36 + c4;
                d[0] = __uint_as_float(f2tf(v.x));
                d[1] = __uint_as_float(f2tf(v.y));
                d[2] = __uint_as_float(f2tf(v.z));
                d[3] = __uint_as_float(f2tf(v.w));
            }
            // B tile 64x32: row r -> W row (r/16)*1024 + j0 + (r%16)  (gate-grouped)
            #pragma unroll
            for (int i = 0; i < 2; i++) {
                int q = tid + i * 256;
                int r = q >> 3, c4 = (q & 7) << 2;
                int wrow = (r >> 4) * HH + j0 + (r & 15);
                const float4 v = *(const float4*)(W + (size_t)wrow * K + k0 + c4);
                float* d = sB + r * 36 + c4;
                d[0] = __uint_as_float(f2tf(v.x));
                d[1] = __uint_as_float(f2tf(v.y));
                d[2] = __uint_as_float(f2tf(v.z));
                d[3] = __uint_as_float(f2tf(v.w));
            }
            __syncthreads();
            const uint32_t* uA = (const uint32_t*)sA;
            const uint32_t* uB = (const uint32_t*)sB;
            #pragma unroll
            for (int ks = 0; ks < 4; ks++) {
                uint32_t af[2][4], bf[4][2];
                #pragma unroll
                for (int im = 0; im < 2; im++) {
                    int mr = wm + im * 16 + gid;
                    af[im][0] = uA[mr * 36 + ks * 8 + tig];
                    af[im][1] = uA[(mr + 8) * 36 + ks * 8 + tig];
                    af[im][2] = uA[mr * 36 + ks * 8 + tig + 4];
                    af[im][3] = uA[(mr + 8) * 36 + ks * 8 + tig + 4];
                }
                #pragma unroll
                for (int in = 0; in < 4; in++) {
                    int nr = wn + in * 8 + gid;
                    bf[in][0] = uB[nr * 36 + ks * 8 + tig];
                    bf[in][1] = uB[nr * 36 + ks * 8 + tig + 4];
                }
                #pragma unroll
                for (int im = 0; im < 2; im++)
                    #pragma unroll
                    for (int in = 0; in < 4; in++)
                        mma8(acc[im][in], af[im][0], af[im][1], af[im][2], af[im][3],
                             bf[in][0], bf[in][1]);
            }
            __syncthreads();
        }
    }

    // ---- epilogue: gather 4 gates per unit via smem, apply LSTM update ----
    float* Gs = sm;   // 128 x 65
    #pragma unroll
    for (int im = 0; im < 2; im++)
        #pragma unroll
        for (int in = 0; in < 4; in++) {
            int m = wm + im * 16 + gid;
            int n = wn + in * 8 + tig * 2;
            Gs[m * 65 + n]           = acc[im][in][0];
            Gs[m * 65 + n + 1]       = acc[im][in][1];
            Gs[(m + 8) * 65 + n]     = acc[im][in][2];
            Gs[(m + 8) * 65 + n + 1] = acc[im][in][3];
        }
    __syncthreads();

    #pragma unroll
    for (int e = tid; e < 2048; e += 256) {     // 128 rows x 16 units
        int m = e >> 4, j = e & 15;
        int unit = j0 + j;
        size_t grow = rowbase + m;
        float gi = Gs[m * 65 + j]      + bih[unit]          + bhh[unit];
        float gf = Gs[m * 65 + 16 + j] + bih[HH + unit]     + bhh[HH + unit];
        float gg = Gs[m * 65 + 32 + j] + bih[2 * HH + unit] + bhh[2 * HH + unit];
        float go = Gs[m * 65 + 48 + j] + bih[3 * HH + unit] + bhh[3 * HH + unit];
        float ii = 1.f / (1.f + expf(-gi));
        float ff = 1.f / (1.f + expf(-gf));
        float gt = tanhf(gg);
        float oo = 1.f / (1.f + expf(-go));
        float c2 = ff * cprev[grow * HH + unit] + ii * gt;
        float h2 = oo * tanhf(c2);
        cout[grow * HH + unit] = c2;
        hout[grow * HH + unit] = h2;
    }
}

// ---------------- output linear: out[rows,128] = A[rows,1024] @ Wlin^T + b ----------------
// BM=64, BN=64, 128 threads. grid.x = 2, grid.y = rows/64.
__global__ __launch_bounds__(128) void linear_kernel(
    const float* __restrict__ A,
    const float* __restrict__ W,     // [128, 1024]
    const float* __restrict__ bias,  // [128]
    float* __restrict__ out)         // [rows, 128]
{
    __shared__ float sm[64 * 36 * 2];
    float* sA = sm;
    float* sB = sm + 64 * 36;

    const int tid  = threadIdx.x;
    const int warp = tid >> 5, lane = tid & 31;
    const int gid  = lane >> 2, tig = lane & 3;
    const int wm   = (warp & 1) * 32;
    const int wn   = (warp >> 1) * 32;
    const int n0   = blockIdx.x * 64;
    const size_t rowbase = (size_t)blockIdx.y * 64;

    float acc[2][4][4];
    #pragma unroll
    for (int i = 0; i < 2; i++)
        #pragma unroll
        for (int j = 0; j < 4; j++)
            #pragma unroll
            for (int q = 0; q < 4; q++) acc[i][j][q] = 0.f;

    for (int k0 = 0; k0 < HH; k0 += 32) {
        #pragma unroll
        for (int i = 0; i < 4; i++) {
            int q = tid + i * 128;
            int r = q >> 3, c4 = (q & 7) << 2;
            const float4 v = *(const float4*)(A + (rowbase + r) * (size_t)HH + k0 + c4);
            float* d = sA + r * 36 + c4;
            d[0] = __uint_as_float(f2tf(v.x));
            d[1] = __uint_as_float(f2tf(v.y));
            d[2] = __uint_as_float(f2tf(v.z));
            d[3] = __uint_as_float(f2tf(v.w));
        }
        #pragma unroll
        for (int i = 0; i < 4; i++) {
            int q = tid + i * 128;
            int r = q >> 3, c4 = (q & 7) << 2;
            const float4 v = *(const float4*)(W + (size_t)(n0 + r) * HH + k0 + c4);
            float* d = sB + r * 36 + c4;
            d[0] = __uint_as_float(f2tf(v.x));
            d[1] = __uint_as_float(f2tf(v.y));
            d[2] = __uint_as_float(f2tf(v.z));
            d[3] = __uint_as_float(f2tf(v.w));
        }
        __syncthreads();
        const uint32_t* uA = (const uint32_t*)sA;
        const uint32_t* uB = (const uint32_t*)sB;
        #pragma unroll
        for (int ks = 0; ks < 4; ks++) {
            uint32_t af[2][4], bf[4][2];
            #pragma unroll
            for (int im = 0; im < 2; im++) {
                int mr = wm + im * 16 + gid;
                af[im][0] = uA[mr * 36 + ks * 8 + tig];
                af[im][1] = uA[(mr + 8) * 36 + ks * 8 + tig];
                af[im][2] = uA[mr * 36 + ks * 8 + tig + 4];
                af[im][3] = uA[(mr + 8) * 36 + ks * 8 + tig + 4];
            }
            #pragma unroll
            for (int in = 0; in < 4; in++) {
                int nr = wn + in * 8 + gid;
                bf[in][0] = uB[nr * 36 + ks * 8 + tig];
                bf[in][1] = uB[nr * 36 + ks * 8 + tig + 4];
            }
            #pragma unroll
            for (int im = 0; im < 2; im++)
                #pragma unroll
                for (int in = 0; in < 4; in++)
                    mma8(acc[im][in], af[im][0], af[im][1], af[im][2], af[im][3],
                         bf[in][0], bf[in][1]);
        }
        __syncthreads();
    }

    #pragma unroll
    for (int im = 0; im < 2; im++)
        #pragma unroll
        for (int in = 0; in < 4; in++) {
            int m = wm + im * 16 + gid;
            int n = wn + in * 8 + tig * 2;
            size_t r0 = rowbase + m;
            out[r0 * FF + n0 + n]           = acc[im][in][0] + bias[n0 + n];
            out[r0 * FF + n0 + n + 1]       = acc[im][in][1] + bias[n0 + n + 1];
            out[(r0 + 8) * FF + n0 + n]     = acc[im][in][2] + bias[n0 + n];
            out[(r0 + 8) * FF + n0 + n + 1] = acc[im][in][3] + bias[n0 + n + 1];
        }
}

// ---------------- init: seed slot 0 with h0/c0 ----------------
__global__ void init_states(const float* __restrict__ h0, const float* __restrict__ c0) {
    int i = blockIdx.x * blockDim.x + threadIdx.x;
    if (i < HS_SLOT) {
        g_hs0[0][i] = h0[i];
        g_hs1[0][i] = h0[HS_SLOT + i];
        g_cs0[i]    = c0[i];
        g_cs1[i]    = c0[HS_SLOT + i];
    }
}

// ---------------- output assembly (gather form of the reference's fill+scatter) ----------------
__global__ void assemble(const float* __restrict__ inMusic, float* __restrict__ out) {
    const size_t OUTM = (size_t)NS * BB * FF * NPRED;      // 12582912
    const size_t HFO  = OUTM;
    const size_t CFO  = HFO + 2 * (size_t)HS_SLOT;
    const size_t NSE  = CFO + 2 * (size_t)HS_SLOT;
    const size_t TOT  = NSE + PRED_SLOT;                   // 13123584
    for (size_t idx = blockIdx.x * (size_t)blockDim.x + threadIdx.x; idx < TOT;
         idx += (size_t)gridDim.x * blockDim.x) {
        float v;
        if (idx < OUTM) {
            int n = (int)(idx & 7);
            int f = (int)((idx >> 3) & 127);
            int b = (int)((idx >> 10) & 127);
            int r = (int)(idx >> 17);
            if (r < NPRED && n >= r)
                v = inMusic[((size_t)r * BB + b) * FF + f];
            else if (r >= 2 * n + 2)
                v = g_preds[n][(size_t)(r - n - 1) * PRED_SLOT + b * FF + f];
            else
                v = 0.f;
        } else if (idx < CFO) {
            size_t i = idx - HFO;
            size_t rest = i & (HS_SLOT - 1);
            v = (i >= HS_SLOT) ? g_hs1[0][95 * (size_t)HS_SLOT + rest]
                               : g_hs0[0][95 * (size_t)HS_SLOT + rest];
        } else if (idx < NSE) {
            size_t i = idx - CFO;
            size_t rest = i & (HS_SLOT - 1);
            v = (i >= HS_SLOT) ? g_cs1[95 * (size_t)HS_SLOT + rest]
                               : g_cs0[95 * (size_t)HS_SLOT + rest];
        } else {
            v = g_preds[0][95 * (size_t)PRED_SLOT + (idx - NSE)];
        }
        out[idx] = v;
    }
}

// ---------------- host orchestration ----------------
extern "C" void kernel_launch(void* const* d_in, const int* in_sizes, int n_in,
                              void* d_out, int out_size) {
    const float* inMusic = (const float*)d_in[0];
    const float* h0   = (const float*)d_in[1];
    const float* c0   = (const float*)d_in[2];
    const float* Wih0 = (const float*)d_in[3];
    const float* Whh0 = (const float*)d_in[4];
    const float* bih0 = (const float*)d_in[5];
    const float* bhh0 = (const float*)d_in[6];
    const float* Wih1 = (const float*)d_in[7];
    const float* Whh1 = (const float*)d_in[8];
    const float* bih1 = (const float*)d_in[9];
    const float* bhh1 = (const float*)d_in[10];
    const float* Wlin = (const float*)d_in[11];
    const float* blin = (const float*)d_in[12];
    float* out = (float*)d_out;

    float *hs0, *hs1, *cs0, *cs1, *preds;
    cudaGetSymbolAddress((void**)&hs0, g_hs0);
    cudaGetSymbolAddress((void**)&hs1, g_hs1);
    cudaGetSymbolAddress((void**)&cs0, g_cs0);
    cudaGetSymbolAddress((void**)&cs1, g_cs1);
    cudaGetSymbolAddress((void**)&preds, g_preds);
    const size_t BUF = (size_t)NS * HS_SLOT;   // per-double-buffer size

    init_states<<<(HS_SLOT + 255) / 256, 256>>>(h0, c0);

    // --- sequential filter chain, k = 1..95 (k=0 is dead work) ---
    for (int k = 1; k < NS; k++) {
        lstm_cell<<<dim3(64, 1), 256>>>(
            inMusic + (size_t)k * PRED_SLOT, FF,
            hs0 + (size_t)(k - 1) * HS_SLOT, Wih0, Whh0, bih0, bhh0,
            cs0 + (size_t)(k - 1) * HS_SLOT,
            hs0 + (size_t)k * HS_SLOT, cs0 + (size_t)k * HS_SLOT);
        lstm_cell<<<dim3(64, 1), 256>>>(
            hs0 + (size_t)k * HS_SLOT, HH,
            hs1 + (size_t)(k - 1) * HS_SLOT, Wih1, Whh1, bih1, bhh1,
            cs1 + (size_t)(k - 1) * HS_SLOT,
            hs1 + (size_t)k * HS_SLOT, cs1 + (size_t)k * HS_SLOT);
    }

    // --- pred0 for k = 1..95 in one batched linear ---
    linear_kernel<<<dim3(2, 95 * 2), 128>>>(hs1 + HS_SLOT, Wlin, blin, preds + PRED_SLOT);

    // --- closed-loop prediction steps, batched across all active k ---
    for (int n = 1; n < NPRED; n++) {
        int k0 = n + 1;
        int nk = 94 - 2 * n;                 // active k in [n+1, 94-n]
        int src = (n - 1) & 1, dst = n & 1;
        size_t off = (size_t)k0 * HS_SLOT;
        lstm_cell<<<dim3(64, nk), 256>>>(
            preds + (size_t)(n - 1) * NS * PRED_SLOT + (size_t)k0 * PRED_SLOT, FF,
            hs0 + src * BUF + off, Wih0, Whh0, bih0, bhh0,
            cs0 + off,
            hs0 + dst * BUF + off, cs0 + off);
        lstm_cell<<<dim3(64, nk), 256>>>(
            hs0 + dst * BUF + off, HH,
            hs1 + src * BUF + off, Wih1, Whh1, bih1, bhh1,
            cs1 + off,
            hs1 + dst * BUF + off, cs1 + off);
        linear_kernel<<<dim3(2, nk * 2), 128>>>(
            hs1 + dst * BUF + off, Wlin, blin,
            preds + (size_t)n * NS * PRED_SLOT + (size_t)k0 * PRED_SLOT);
    }

    assemble<<<4096, 256>>>(inMusic, out);
    (void)in_sizes; (void)n_in; (void)out_size;
}

// round 5
// speedup vs baseline: 1.1482x; 1.1482x over previous
#include <cuda_runtime.h>
#include <cstdint>

#define BB 128     // batch
#define HH 1024    // hidden
#define FF 128     // features
#define NS 96      // samples
#define NPRED 8    // horizon
#define HS_SLOT (BB*HH)     // 131072
#define PRED_SLOT (BB*FF)   // 16384

// ---------------- device scratch (static: no allocations allowed) ----------------
__device__ float g_hs0[2][NS*HS_SLOT];
__device__ float g_hs1[2][NS*HS_SLOT];
__device__ float g_cs0[NS*HS_SLOT];
__device__ float g_cs1[NS*HS_SLOT];
__device__ float g_preds[NPRED][NS*PRED_SLOT];
__device__ float g_scratch[8 * 128 * 4096];     // split-K partials (16MB)

// ---------------- helpers ----------------
__device__ __forceinline__ uint32_t f2tf(float x) {
    uint32_t r;
    asm("cvt.rna.tf32.f32 %0, %1;" : "=r"(r) : "f"(x));
    return r;
}

__device__ __forceinline__ void mma8(float* c, uint32_t a0, uint32_t a1, uint32_t a2,
                                     uint32_t a3, uint32_t b0, uint32_t b1) {
    asm volatile(
        "mma.sync.aligned.m16n8k8.row.col.f32.tf32.tf32.f32 "
        "{%0,%1,%2,%3},{%4,%5,%6,%7},{%8,%9},{%0,%1,%2,%3};\n"
        : "+f"(c[0]), "+f"(c[1]), "+f"(c[2]), "+f"(c[3])
        : "r"(a0), "r"(a1), "r"(a2), "r"(a3), "r"(b0), "r"(b1));
}

__device__ __forceinline__ float sigf(float x) { return 1.f / (1.f + __expf(-x)); }

// =====================================================================
// Chain cell main: BM=128 x BN=64, split-K over gridDim.z, partials to scratch.
// grid (64, 1, SPLIT), 256 threads. Synchronous loads (round-2 proven style).
// =====================================================================
__global__ __launch_bounds__(256) void lstm_chain_main(
    const float* __restrict__ Ax, int Kx,
    const float* __restrict__ Ah,
    const float* __restrict__ Wih, const float* __restrict__ Whh,
    float* __restrict__ scratch, int chunksPer)
{
    __shared__ float sm[128 * 36 + 64 * 36];
    float* sA = sm;
    float* sB = sm + 128 * 36;

    const int tid  = threadIdx.x;
    const int warp = tid >> 5, lane = tid & 31;
    const int gid  = lane >> 2, tig = lane & 3;
    const int wm   = (warp & 3) * 32;
    const int wn   = (warp >> 2) * 32;
    const int j0   = blockIdx.x * 16;
    const int nx   = Kx >> 5;
    const int c0   = blockIdx.z * chunksPer, c1 = c0 + chunksPer;

    float acc[2][4][4];
    #pragma unroll
    for (int i = 0; i < 2; i++)
        #pragma unroll
        for (int j = 0; j < 4; j++)
            #pragma unroll
            for (int q = 0; q < 4; q++) acc[i][j][q] = 0.f;

    for (int c = c0; c < c1; c++) {
        const float *A, *W; int K, k0;
        if (c < nx) { A = Ax; W = Wih; K = Kx; k0 = c << 5; }
        else        { A = Ah; W = Whh; K = HH; k0 = (c - nx) << 5; }
        #pragma unroll
        for (int i = 0; i < 4; i++) {
            int q = tid + (i << 8);
            int r = q >> 3, c4 = (q & 7) << 2;
            const float4 v = *(const float4*)(A + (size_t)r * K + k0 + c4);
            float* d = sA + r * 36 + c4;
            d[0] = __uint_as_float(f2tf(v.x));
            d[1] = __uint_as_float(f2tf(v.y));
            d[2] = __uint_as_float(f2tf(v.z));
            d[3] = __uint_as_float(f2tf(v.w));
        }
        #pragma unroll
        for (int i = 0; i < 2; i++) {
            int q = tid + (i << 8);
            int r = q >> 3, c4 = (q & 7) << 2;
            int wr = (r >> 4) * HH + j0 + (r & 15);
            const float4 v = *(const float4*)(W + (size_t)wr * K + k0 + c4);
            float* d = sB + r * 36 + c4;
            d[0] = __uint_as_float(f2tf(v.x));
            d[1] = __uint_as_float(f2tf(v.y));
            d[2] = __uint_as_float(f2tf(v.z));
            d[3] = __uint_as_float(f2tf(v.w));
        }
        __syncthreads();
        const uint32_t* uA = (const uint32_t*)sA;
        const uint32_t* uB = (const uint32_t*)sB;
        #pragma unroll
        for (int ks = 0; ks < 4; ks++) {
            uint32_t af[2][4], bf[4][2];
            #pragma unroll
            for (int im = 0; im < 2; im++) {
                int mr = wm + im * 16 + gid;
                af[im][0] = uA[mr * 36 + ks * 8 + tig];
                af[im][1] = uA[(mr + 8) * 36 + ks * 8 + tig];
                af[im][2] = uA[mr * 36 + ks * 8 + tig + 4];
                af[im][3] = uA[(mr + 8) * 36 + ks * 8 + tig + 4];
            }
            #pragma unroll
            for (int in = 0; in < 4; in++) {
                int nr = wn + in * 8 + gid;
                bf[in][0] = uB[nr * 36 + ks * 8 + tig];
                bf[in][1] = uB[nr * 36 + ks * 8 + tig + 4];
            }
            #pragma unroll
            for (int im = 0; im < 2; im++)
                #pragma unroll
                for (int in = 0; in < 4; in++)
                    mma8(acc[im][in], af[im][0], af[im][1], af[im][2], af[im][3],
                         bf[in][0], bf[in][1]);
        }
        __syncthreads();
    }

    // store partials: col = gate*1024 + unit
    size_t base = (size_t)blockIdx.z * 128 * 4096;
    #pragma unroll
    for (int im = 0; im < 2; im++)
        #pragma unroll
        for (int in = 0; in < 4; in++) {
            int m = wm + im * 16 + gid;
            int nl = wn + in * 8 + tig * 2;
            int gc = (nl >> 4) * HH + j0 + (nl & 15);
            float2 v;
            v.x = acc[im][in][0]; v.y = acc[im][in][1];
            *(float2*)&scratch[base + (size_t)m * 4096 + gc] = v;
            v.x = acc[im][in][2]; v.y = acc[im][in][3];
            *(float2*)&scratch[base + (size_t)(m + 8) * 4096 + gc] = v;
        }
}

// ---------------- chain reduce + gates ----------------
__global__ void lstm_reduce(const float* __restrict__ scr, int nsplit,
    const float* __restrict__ bih, const float* __restrict__ bhh,
    const float* __restrict__ cprev, float* __restrict__ hout, float* __restrict__ cout)
{
    int idx = blockIdx.x * blockDim.x + threadIdx.x;   // grid 512x256
    int m = idx >> 10, u = idx & 1023;
    float gi = bih[u] + bhh[u];
    float gf = bih[HH + u] + bhh[HH + u];
    float gg = bih[2 * HH + u] + bhh[2 * HH + u];
    float go = bih[3 * HH + u] + bhh[3 * HH + u];
    for (int s = 0; s < nsplit; s++) {
        const float* p = scr + ((size_t)(s * 128 + m)) * 4096;
        gi += p[u]; gf += p[HH + u]; gg += p[2 * HH + u]; go += p[3 * HH + u];
    }
    float c2 = sigf(gf) * cprev[idx] + sigf(gi) * tanhf(gg);
    cout[idx] = c2;
    hout[idx] = sigf(go) * tanhf(c2);
}

// =====================================================================
// Batched inner cell: BM=128 x BN=128 (32 units x 4 gates), fused epilogue.
// grid (32, nrowblocks), 256 threads, 73728B dyn smem (2-stage sync loads).
// =====================================================================
__global__ __launch_bounds__(256) void lstm_big(
    const float* __restrict__ Ax, int Kx,
    const float* __restrict__ Ah,
    const float* __restrict__ Wih, const float* __restrict__ Whh,
    const float* __restrict__ bih, const float* __restrict__ bhh,
    const float* __restrict__ cprev, float* __restrict__ hout, float* __restrict__ cout)
{
    extern __shared__ float sm[];   // A:128x36 + B:128x36 = 9216 floats
    float* sA = sm;
    float* sB = sm + 128 * 36;

    const int tid  = threadIdx.x;
    const int warp = tid >> 5, lane = tid & 31;
    const int gid  = lane >> 2, tig = lane & 3;
    const int wm   = (warp & 3) * 32;            // 4 warps along M (128)
    const int wn   = (warp >> 2) * 64;           // 2 warps along N (128)
    const int j0   = blockIdx.x * 32;            // unit block (32 units)
    const size_t rowbase = (size_t)blockIdx.y * 128;
    const int nx = Kx >> 5, C = nx + 32;

    float acc[2][8][4];
    #pragma unroll
    for (int i = 0; i < 2; i++)
        #pragma unroll
        for (int j = 0; j < 8; j++)
            #pragma unroll
            for (int q = 0; q < 4; q++) acc[i][j][q] = 0.f;

    for (int c = 0; c < C; c++) {
        const float *A, *W; int K, k0;
        if (c < nx) { A = Ax; W = Wih; K = Kx; k0 = c << 5; }
        else        { A = Ah; W = Whh; K = HH; k0 = (c - nx) << 5; }
        #pragma unroll
        for (int i = 0; i < 4; i++) {
            int q = tid + (i << 8);
            int r = q >> 3, c4 = (q & 7) << 2;
            const float4 v = *(const float4*)(A + (rowbase + r) * (size_t)K + k0 + c4);
            float* d = sA + r * 36 + c4;
            d[0] = __uint_as_float(f2tf(v.x));
            d[1] = __uint_as_float(f2tf(v.y));
            d[2] = __uint_as_float(f2tf(v.z));
            d[3] = __uint_as_float(f2tf(v.w));
        }
        #pragma unroll
        for (int i = 0; i < 4; i++) {
            int q = tid + (i << 8);
            int r = q >> 3, c4 = (q & 7) << 2;
            int wr = (r >> 5) * HH + j0 + (r & 31);   // gate-grouped: 32 units x 4 gates
            const float4 v = *(const float4*)(W + (size_t)wr * K + k0 + c4);
            float* d = sB + r * 36 + c4;
            d[0] = __uint_as_float(f2tf(v.x));
            d[1] = __uint_as_float(f2tf(v.y));
            d[2] = __uint_as_float(f2tf(v.z));
            d[3] = __uint_as_float(f2tf(v.w));
        }
        __syncthreads();
        const uint32_t* uA = (const uint32_t*)sA;
        const uint32_t* uB = (const uint32_t*)sB;
        #pragma unroll
        for (int ks = 0; ks < 4; ks++) {
            uint32_t af[2][4], bf[8][2];
            #pragma unroll
            for (int im = 0; im < 2; im++) {
                int mr = wm + im * 16 + gid;
                af[im][0] = uA[mr * 36 + ks * 8 + tig];
                af[im][1] = uA[(mr + 8) * 36 + ks * 8 + tig];
                af[im][2] = uA[mr * 36 + ks * 8 + tig + 4];
                af[im][3] = uA[(mr + 8) * 36 + ks * 8 + tig + 4];
            }
            #pragma unroll
            for (int in = 0; in < 8; in++) {
                int nr = wn + in * 8 + gid;
                bf[in][0] = uB[nr * 36 + ks * 8 + tig];
                bf[in][1] = uB[nr * 36 + ks * 8 + tig + 4];
            }
            #pragma unroll
            for (int im = 0; im < 2; im++)
                #pragma unroll
                for (int in = 0; in < 8; in++)
                    mma8(acc[im][in], af[im][0], af[im][1], af[im][2], af[im][3],
                         bf[in][0], bf[in][1]);
        }
        __syncthreads();
    }

    // ---- epilogue ----
    // wn=0 warps hold gates i (in 0..3) and f (in 4..7); wn=64 hold g and o.
    if (wn == 64) {     // exchange: g at sm[0..4095], o at sm[4096..8191]
        #pragma unroll
        for (int im = 0; im < 2; im++)
            #pragma unroll
            for (int in = 0; in < 4; in++) {
                int m = wm + im * 16 + gid;
                int u = in * 8 + tig * 2;
                float2 v;
                v.x = acc[im][in][0];     v.y = acc[im][in][1];
                *(float2*)&sm[m * 32 + u] = v;
                v.x = acc[im][in + 4][0]; v.y = acc[im][in + 4][1];
                *(float2*)&sm[4096 + m * 32 + u] = v;
                v.x = acc[im][in][2];     v.y = acc[im][in][3];
                *(float2*)&sm[(m + 8) * 32 + u] = v;
                v.x = acc[im][in + 4][2]; v.y = acc[im][in + 4][3];
                *(float2*)&sm[4096 + (m + 8) * 32 + u] = v;
            }
    }
    __syncthreads();
    if (wn == 0) {
        #pragma unroll
        for (int im = 0; im < 2; im++)
            #pragma unroll
            for (int in = 0; in < 4; in++)
                #pragma unroll
                for (int half = 0; half < 2; half++) {
                    int m = wm + im * 16 + gid + half * 8;
                    #pragma unroll
                    for (int du = 0; du < 2; du++) {
                        int u = in * 8 + tig * 2 + du;
                        int unit = j0 + u;
                        float gi = acc[im][in][half * 2 + du]     + bih[unit] + bhh[unit];
                        float gf = acc[im][in + 4][half * 2 + du] + bih[HH + unit] + bhh[HH + unit];
                        float gg = sm[m * 32 + u]        + bih[2 * HH + unit] + bhh[2 * HH + unit];
                        float go = sm[4096 + m * 32 + u] + bih[3 * HH + unit] + bhh[3 * HH + unit];
                        size_t off = (rowbase + m) * HH + unit;
                        float c2 = sigf(gf) * cprev[off] + sigf(gi) * tanhf(gg);
                        cout[off] = c2;
                        hout[off] = sigf(go) * tanhf(c2);
                    }
                }
    }
}

// ---------------- output linear: out[rows,128] = A[rows,1024] @ Wlin^T + b ----------------
__global__ __launch_bounds__(128) void linear_kernel(
    const float* __restrict__ A,
    const float* __restrict__ W,
    const float* __restrict__ bias,
    float* __restrict__ out)
{
    __shared__ float sml[64 * 36 * 2];
    float* sA = sml;
    float* sB = sml + 64 * 36;

    const int tid  = threadIdx.x;
    const int warp = tid >> 5, lane = tid & 31;
    const int gid  = lane >> 2, tig = lane & 3;
    const int wm   = (warp & 1) * 32;
    const int wn   = (warp >> 1) * 32;
    const int n0   = blockIdx.x * 64;
    const size_t rowbase = (size_t)blockIdx.y * 64;

    float acc[2][4][4];
    #pragma unroll
    for (int i = 0; i < 2; i++)
        #pragma unroll
        for (int j = 0; j < 4; j++)
            #pragma unroll
            for (int q = 0; q < 4; q++) acc[i][j][q] = 0.f;

    for (int k0 = 0; k0 < HH; k0 += 32) {
        #pragma unroll
        for (int i = 0; i < 4; i++) {
            int q = tid + i * 128;
            int r = q >> 3, c4 = (q & 7) << 2;
            const float4 v = *(const float4*)(A + (rowbase + r) * (size_t)HH + k0 + c4);
            float* d = sA + r * 36 + c4;
            d[0] = __uint_as_float(f2tf(v.x));
            d[1] = __uint_as_float(f2tf(v.y));
            d[2] = __uint_as_float(f2tf(v.z));
            d[3] = __uint_as_float(f2tf(v.w));
        }
        #pragma unroll
        for (int i = 0; i < 4; i++) {
            int q = tid + i * 128;
            int r = q >> 3, c4 = (q & 7) << 2;
            const float4 v = *(const float4*)(W + (size_t)(n0 + r) * HH + k0 + c4);
            float* d = sB + r * 36 + c4;
            d[0] = __uint_as_float(f2tf(v.x));
            d[1] = __uint_as_float(f2tf(v.y));
            d[2] = __uint_as_float(f2tf(v.z));
            d[3] = __uint_as_float(f2tf(v.w));
        }
        __syncthreads();
        const uint32_t* uA = (const uint32_t*)sA;
        const uint32_t* uB = (const uint32_t*)sB;
        #pragma unroll
        for (int ks = 0; ks < 4; ks++) {
            uint32_t af[2][4], bf[4][2];
            #pragma unroll
            for (int im = 0; im < 2; im++) {
                int mr = wm + im * 16 + gid;
                af[im][0] = uA[mr * 36 + ks * 8 + tig];
                af[im][1] = uA[(mr + 8) * 36 + ks * 8 + tig];
                af[im][2] = uA[mr * 36 + ks * 8 + tig + 4];
                af[im][3] = uA[(mr + 8) * 36 + ks * 8 + tig + 4];
            }
            #pragma unroll
            for (int in = 0; in < 4; in++) {
                int nr = wn + in * 8 + gid;
                bf[in][0] = uB[nr * 36 + ks * 8 + tig];
                bf[in][1] = uB[nr * 36 + ks * 8 + tig + 4];
            }
            #pragma unroll
            for (int im = 0; im < 2; im++)
                #pragma unroll
                for (int in = 0; in < 4; in++)
                    mma8(acc[im][in], af[im][0], af[im][1], af[im][2], af[im][3],
                         bf[in][0], bf[in][1]);
        }
        __syncthreads();
    }

    #pragma unroll
    for (int im = 0; im < 2; im++)
        #pragma unroll
        for (int in = 0; in < 4; in++) {
            int m = wm + im * 16 + gid;
            int n = wn + in * 8 + tig * 2;
            size_t r0 = rowbase + m;
            out[r0 * FF + n0 + n]           = acc[im][in][0] + bias[n0 + n];
            out[r0 * FF + n0 + n + 1]       = acc[im][in][1] + bias[n0 + n + 1];
            out[(r0 + 8) * FF + n0 + n]     = acc[im][in][2] + bias[n0 + n];
            out[(r0 + 8) * FF + n0 + n + 1] = acc[im][in][3] + bias[n0 + n + 1];
        }
}

// ---------------- init ----------------
__global__ void init_states(const float* __restrict__ h0, const float* __restrict__ c0) {
    int i = blockIdx.x * blockDim.x + threadIdx.x;
    if (i < HS_SLOT) {
        g_hs0[0][i] = h0[i];
        g_hs1[0][i] = h0[HS_SLOT + i];
        g_cs0[i]    = c0[i];
        g_cs1[i]    = c0[HS_SLOT + i];
    }
}

// ---------------- output assembly ----------------
__global__ void assemble(const float* __restrict__ inMusic, float* __restrict__ out) {
    const size_t OUTM = (size_t)NS * BB * FF * NPRED;
    const size_t HFO  = OUTM;
    const size_t CFO  = HFO + 2 * (size_t)HS_SLOT;
    const size_t NSE  = CFO + 2 * (size_t)HS_SLOT;
    const size_t TOT  = NSE + PRED_SLOT;
    for (size_t idx = blockIdx.x * (size_t)blockDim.x + threadIdx.x; idx < TOT;
         idx += (size_t)gridDim.x * blockDim.x) {
        float v;
        if (idx < OUTM) {
            int n = (int)(idx & 7);
            int f = (int)((idx >> 3) & 127);
            int b = (int)((idx >> 10) & 127);
            int r = (int)(idx >> 17);
            if (r < NPRED && n >= r)
                v = inMusic[((size_t)r * BB + b) * FF + f];
            else if (r >= 2 * n + 2)
                v = g_preds[n][(size_t)(r - n - 1) * PRED_SLOT + b * FF + f];
            else
                v = 0.f;
        } else if (idx < CFO) {
            size_t i = idx - HFO;
            size_t rest = i & (HS_SLOT - 1);
            v = (i >= HS_SLOT) ? g_hs1[0][95 * (size_t)HS_SLOT + rest]
                               : g_hs0[0][95 * (size_t)HS_SLOT + rest];
        } else if (idx < NSE) {
            size_t i = idx - CFO;
            size_t rest = i & (HS_SLOT - 1);
            v = (i >= HS_SLOT) ? g_cs1[95 * (size_t)HS_SLOT + rest]
                               : g_cs0[95 * (size_t)HS_SLOT + rest];
        } else {
            v = g_preds[0][95 * (size_t)PRED_SLOT + (idx - NSE)];
        }
        out[idx] = v;
    }
}

// ---------------- host orchestration ----------------
extern "C" void kernel_launch(void* const* d_in, const int* in_sizes, int n_in,
                              void* d_out, int out_size) {
    const float* inMusic = (const float*)d_in[0];
    const float* h0   = (const float*)d_in[1];
    const float* c0   = (const float*)d_in[2];
    const float* Wih0 = (const float*)d_in[3];
    const float* Whh0 = (const float*)d_in[4];
    const float* bih0 = (const float*)d_in[5];
    const float* bhh0 = (const float*)d_in[6];
    const float* Wih1 = (const float*)d_in[7];
    const float* Whh1 = (const float*)d_in[8];
    const float* bih1 = (const float*)d_in[9];
    const float* bhh1 = (const float*)d_in[10];
    const float* Wlin = (const float*)d_in[11];
    const float* blin = (const float*)d_in[12];
    float* out = (float*)d_out;

    float *hs0, *hs1, *cs0, *cs1, *preds, *scr;
    cudaGetSymbolAddress((void**)&hs0, g_hs0);
    cudaGetSymbolAddress((void**)&hs1, g_hs1);
    cudaGetSymbolAddress((void**)&cs0, g_cs0);
    cudaGetSymbolAddress((void**)&cs1, g_cs1);
    cudaGetSymbolAddress((void**)&preds, g_preds);
    cudaGetSymbolAddress((void**)&scr, g_scratch);
    const size_t BUF = (size_t)NS * HS_SLOT;

    const int SMEM_BIG = 9216 * 4;   // 36864
    cudaFuncSetAttribute(lstm_big, cudaFuncAttributeMaxDynamicSharedMemorySize, SMEM_BIG);

    init_states<<<(HS_SLOT + 255) / 256, 256>>>(h0, c0);

    // --- sequential filter chain, k = 1..95 (split-K + reduce) ---
    for (int k = 1; k < NS; k++) {
        lstm_chain_main<<<dim3(64, 1, 6), 256>>>(
            inMusic + (size_t)k * PRED_SLOT, FF,
            hs0 + (size_t)(k - 1) * HS_SLOT, Wih0, Whh0, scr, 6);
        lstm_reduce<<<512, 256>>>(scr, 6, bih0, bhh0,
            cs0 + (size_t)(k - 1) * HS_SLOT,
            hs0 + (size_t)k * HS_SLOT, cs0 + (size_t)k * HS_SLOT);
        lstm_chain_main<<<dim3(64, 1, 8), 256>>>(
            hs0 + (size_t)k * HS_SLOT, HH,
            hs1 + (size_t)(k - 1) * HS_SLOT, Wih1, Whh1, scr, 8);
        lstm_reduce<<<512, 256>>>(scr, 8, bih1, bhh1,
            cs1 + (size_t)(k - 1) * HS_SLOT,
            hs1 + (size_t)k * HS_SLOT, cs1 + (size_t)k * HS_SLOT);
    }

    // --- pred0 for k = 1..95 ---
    linear_kernel<<<dim3(2, 95 * 2), 128>>>(hs1 + HS_SLOT, Wlin, blin, preds + PRED_SLOT);

    // --- closed-loop prediction steps, batched across active k ---
    for (int n = 1; n < NPRED; n++) {
        int k0 = n + 1;
        int nk = 94 - 2 * n;                 // active k in [n+1, 94-n]
        int src = (n - 1) & 1, dst = n & 1;
        size_t off = (size_t)k0 * HS_SLOT;
        lstm_big<<<dim3(32, nk), 256, SMEM_BIG>>>(
            preds + (size_t)(n - 1) * NS * PRED_SLOT + (size_t)k0 * PRED_SLOT, FF,
            hs0 + src * BUF + off, Wih0, Whh0, bih0, bhh0,
            cs0 + off, hs0 + dst * BUF + off, cs0 + off);
        lstm_big<<<dim3(32, nk), 256, SMEM_BIG>>>(
            hs0 + dst * BUF + off, HH,
            hs1 + src * BUF + off, Wih1, Whh1, bih1, bhh1,
            cs1 + off, hs1 + dst * BUF + off, cs1 + off);
        linear_kernel<<<dim3(2, nk * 2), 128>>>(
            hs1 + dst * BUF + off, Wlin, blin,
            preds + (size_t)n * NS * PRED_SLOT + (size_t)k0 * PRED_SLOT);
    }

    assemble<<<4096, 256>>>(inMusic, out);
    (void)in_sizes; (void)n_in; (void)out_size;
}

// round 6
// speedup vs baseline: 1.1700x; 1.0190x over previous
#include <cuda_runtime.h>
#include <cstdint>

#define BB 128     // batch
#define HH 1024    // hidden
#define FF 128     // features
#define NS 96      // samples
#define NPRED 8    // horizon
#define HS_SLOT (BB*HH)     // 131072
#define PRED_SLOT (BB*FF)   // 16384

// ---------------- device scratch (static: no allocations allowed) ----------------
__device__ float g_hs0[2][NS*HS_SLOT];
__device__ float g_hs1[2][NS*HS_SLOT];
__device__ float g_cs0[NS*HS_SLOT];
__device__ float g_cs1[NS*HS_SLOT];
__device__ float g_preds[NPRED][NS*PRED_SLOT];
__device__ float g_gates0[BB * 4096];   // L0 gate accum, pre-loaded with bias sums
__device__ float g_gates1[BB * 4096];   // L1 gate accum
__device__ int   g_cnt0[64];            // split-K arrival counters (always 0 at kernel boundaries)
__device__ int   g_cnt1[64];

// ---------------- helpers ----------------
__device__ __forceinline__ uint32_t f2tf(float x) {
    uint32_t r;
    asm("cvt.rna.tf32.f32 %0, %1;" : "=r"(r) : "f"(x));
    return r;
}

__device__ __forceinline__ void mma8(float* c, uint32_t a0, uint32_t a1, uint32_t a2,
                                     uint32_t a3, uint32_t b0, uint32_t b1) {
    asm volatile(
        "mma.sync.aligned.m16n8k8.row.col.f32.tf32.tf32.f32 "
        "{%0,%1,%2,%3},{%4,%5,%6,%7},{%8,%9},{%0,%1,%2,%3};\n"
        : "+f"(c[0]), "+f"(c[1]), "+f"(c[2]), "+f"(c[3])
        : "r"(a0), "r"(a1), "r"(a2), "r"(a3), "r"(b0), "r"(b1));
}

__device__ __forceinline__ float sigf(float x) { return 1.f / (1.f + __expf(-x)); }

__device__ __forceinline__ void st4tf(float* d, float4 v) {
    d[0] = __uint_as_float(f2tf(v.x));
    d[1] = __uint_as_float(f2tf(v.y));
    d[2] = __uint_as_float(f2tf(v.z));
    d[3] = __uint_as_float(f2tf(v.w));
}

// =====================================================================
// Fused chain cell: BM=128 x BN=64 per CTA, split-K over gridDim.z.
// Split CTAs RED.ADD partial gates into a bias-preloaded buffer; the last
// CTA per column block applies the LSTM update and re-arms the buffer.
// grid (64, 1, SPLIT), 256 threads. Register-prefetch double buffering.
// =====================================================================
__global__ __launch_bounds__(256) void lstm_chain_fused(
    const float* __restrict__ Ax, int Kx,
    const float* __restrict__ Ah,
    const float* __restrict__ Wih, const float* __restrict__ Whh,
    float* __restrict__ gates, int* __restrict__ cnt,
    int nsplit, int chunksPer,
    const float* __restrict__ bih, const float* __restrict__ bhh,
    const float* __restrict__ cprev,
    float* __restrict__ hout, float* __restrict__ cout)
{
    __shared__ float sm[128 * 36 + 64 * 36];
    __shared__ int isLast;
    float* sA = sm;
    float* sB = sm + 128 * 36;

    const int tid  = threadIdx.x;
    const int warp = tid >> 5, lane = tid & 31;
    const int gid  = lane >> 2, tig = lane & 3;
    const int wm   = (warp & 3) * 32;
    const int wn   = (warp >> 2) * 32;
    const int j0   = blockIdx.x * 16;
    const int nx   = Kx >> 5;
    const int c0   = blockIdx.z * chunksPer, c1 = c0 + chunksPer;
    const int c4   = (tid & 7) << 2;          // column within 32-chunk
    const int rbase = tid >> 3;               // 0..31

    float acc[2][4][4];
    #pragma unroll
    for (int i = 0; i < 2; i++)
        #pragma unroll
        for (int j = 0; j < 4; j++)
            #pragma unroll
            for (int q = 0; q < 4; q++) acc[i][j][q] = 0.f;

    float4 pA[4], pB[2];
    auto issue = [&](int c) {
        const float *A, *W; int K, k0;
        if (c < nx) { A = Ax; W = Wih; K = Kx; k0 = c << 5; }
        else        { A = Ah; W = Whh; K = HH; k0 = (c - nx) << 5; }
        #pragma unroll
        for (int i = 0; i < 4; i++) {
            int r = rbase + i * 32;
            pA[i] = *(const float4*)(A + (size_t)r * K + k0 + c4);
        }
        #pragma unroll
        for (int i = 0; i < 2; i++) {
            int r = rbase + i * 32;
            int wr = (r >> 4) * HH + j0 + (r & 15);
            pB[i] = *(const float4*)(W + (size_t)wr * K + k0 + c4);
        }
    };

    issue(c0);
    for (int c = c0; c < c1; c++) {
        #pragma unroll
        for (int i = 0; i < 4; i++) st4tf(sA + (rbase + i * 32) * 36 + c4, pA[i]);
        #pragma unroll
        for (int i = 0; i < 2; i++) st4tf(sB + (rbase + i * 32) * 36 + c4, pB[i]);
        __syncthreads();
        if (c + 1 < c1) issue(c + 1);
        const uint32_t* uA = (const uint32_t*)sA;
        const uint32_t* uB = (const uint32_t*)sB;
        #pragma unroll
        for (int ks = 0; ks < 4; ks++) {
            uint32_t af[2][4], bf[4][2];
            #pragma unroll
            for (int im = 0; im < 2; im++) {
                int mr = wm + im * 16 + gid;
                af[im][0] = uA[mr * 36 + ks * 8 + tig];
                af[im][1] = uA[(mr + 8) * 36 + ks * 8 + tig];
                af[im][2] = uA[mr * 36 + ks * 8 + tig + 4];
                af[im][3] = uA[(mr + 8) * 36 + ks * 8 + tig + 4];
            }
            #pragma unroll
            for (int in = 0; in < 4; in++) {
                int nr = wn + in * 8 + gid;
                bf[in][0] = uB[nr * 36 + ks * 8 + tig];
                bf[in][1] = uB[nr * 36 + ks * 8 + tig + 4];
            }
            #pragma unroll
            for (int im = 0; im < 2; im++)
                #pragma unroll
                for (int in = 0; in < 4; in++)
                    mma8(acc[im][in], af[im][0], af[im][1], af[im][2], af[im][3],
                         bf[in][0], bf[in][1]);
        }
        __syncthreads();
    }

    // ---- accumulate partials into gate buffer (RED.ADD, no return) ----
    #pragma unroll
    for (int im = 0; im < 2; im++)
        #pragma unroll
        for (int in = 0; in < 4; in++) {
            int m = wm + im * 16 + gid;
            int nl = wn + in * 8 + tig * 2;
            int gc = (nl >> 4) * HH + j0 + (nl & 15);
            atomicAdd(&gates[(size_t)m * 4096 + gc],     acc[im][in][0]);
            atomicAdd(&gates[(size_t)m * 4096 + gc + 1], acc[im][in][1]);
            atomicAdd(&gates[(size_t)(m + 8) * 4096 + gc],     acc[im][in][2]);
            atomicAdd(&gates[(size_t)(m + 8) * 4096 + gc + 1], acc[im][in][3]);
        }

    __threadfence();
    __syncthreads();
    if (tid == 0) {
        int old = atomicAdd(cnt + blockIdx.x, 1);
        isLast = (old == nsplit - 1);
    }
    __syncthreads();

    if (isLast) {
        __threadfence();
        #pragma unroll
        for (int e = tid; e < 2048; e += 256) {       // 128 rows x 16 units
            int m = e >> 4, j = e & 15;
            int unit = j0 + j;
            float gi = __ldcg(&gates[(size_t)m * 4096 + unit]);
            float gf = __ldcg(&gates[(size_t)m * 4096 + HH + unit]);
            float gg = __ldcg(&gates[(size_t)m * 4096 + 2 * HH + unit]);
            float go = __ldcg(&gates[(size_t)m * 4096 + 3 * HH + unit]);
            float c2 = sigf(gf) * cprev[(size_t)m * HH + unit] + sigf(gi) * tanhf(gg);
            cout[(size_t)m * HH + unit] = c2;
            hout[(size_t)m * HH + unit] = sigf(go) * tanhf(c2);
            // re-arm buffer for the next step
            gates[(size_t)m * 4096 + unit]          = bih[unit] + bhh[unit];
            gates[(size_t)m * 4096 + HH + unit]     = bih[HH + unit] + bhh[HH + unit];
            gates[(size_t)m * 4096 + 2 * HH + unit] = bih[2 * HH + unit] + bhh[2 * HH + unit];
            gates[(size_t)m * 4096 + 3 * HH + unit] = bih[3 * HH + unit] + bhh[3 * HH + unit];
        }
        if (tid == 0) cnt[blockIdx.x] = 0;
    }
}

// =====================================================================
// Batched inner cell: BM=128 x BN=128 (32 units x 4 gates), fused epilogue,
// register-prefetch double buffering. grid (32, nk), 256 threads.
// =====================================================================
__global__ __launch_bounds__(256) void lstm_big(
    const float* __restrict__ Ax, int Kx,
    const float* __restrict__ Ah,
    const float* __restrict__ Wih, const float* __restrict__ Whh,
    const float* __restrict__ bih, const float* __restrict__ bhh,
    const float* __restrict__ cprev, float* __restrict__ hout, float* __restrict__ cout)
{
    extern __shared__ float sm[];   // A:128x36 + B:128x36 = 9216 floats
    float* sA = sm;
    float* sB = sm + 128 * 36;

    const int tid  = threadIdx.x;
    const int warp = tid >> 5, lane = tid & 31;
    const int gid  = lane >> 2, tig = lane & 3;
    const int wm   = (warp & 3) * 32;            // 4 warps along M (128)
    const int wn   = (warp >> 2) * 64;           // 2 warps along N (128)
    const int j0   = blockIdx.x * 32;            // unit block (32 units)
    const size_t rowbase = (size_t)blockIdx.y * 128;
    const int nx = Kx >> 5, C = nx + 32;
    const int c4 = (tid & 7) << 2;
    const int rbase = tid >> 3;

    float acc[2][8][4];
    #pragma unroll
    for (int i = 0; i < 2; i++)
        #pragma unroll
        for (int j = 0; j < 8; j++)
            #pragma unroll
            for (int q = 0; q < 4; q++) acc[i][j][q] = 0.f;

    float4 pA[4], pB[4];
    auto issue = [&](int c) {
        const float *A, *W; int K, k0;
        if (c < nx) { A = Ax; W = Wih; K = Kx; k0 = c << 5; }
        else        { A = Ah; W = Whh; K = HH; k0 = (c - nx) << 5; }
        #pragma unroll
        for (int i = 0; i < 4; i++) {
            int r = rbase + i * 32;
            pA[i] = *(const float4*)(A + (rowbase + r) * (size_t)K + k0 + c4);
        }
        #pragma unroll
        for (int i = 0; i < 4; i++) {
            int r = rbase + i * 32;
            int wr = (r >> 5) * HH + j0 + (r & 31);
            pB[i] = *(const float4*)(W + (size_t)wr * K + k0 + c4);
        }
    };

    issue(0);
    for (int c = 0; c < C; c++) {
        #pragma unroll
        for (int i = 0; i < 4; i++) st4tf(sA + (rbase + i * 32) * 36 + c4, pA[i]);
        #pragma unroll
        for (int i = 0; i < 4; i++) st4tf(sB + (rbase + i * 32) * 36 + c4, pB[i]);
        __syncthreads();
        if (c + 1 < C) issue(c + 1);
        const uint32_t* uA = (const uint32_t*)sA;
        const uint32_t* uB = (const uint32_t*)sB;
        #pragma unroll
        for (int ks = 0; ks < 4; ks++) {
            uint32_t af[2][4], bf[8][2];
            #pragma unroll
            for (int im = 0; im < 2; im++) {
                int mr = wm + im * 16 + gid;
                af[im][0] = uA[mr * 36 + ks * 8 + tig];
                af[im][1] = uA[(mr + 8) * 36 + ks * 8 + tig];
                af[im][2] = uA[mr * 36 + ks * 8 + tig + 4];
                af[im][3] = uA[(mr + 8) * 36 + ks * 8 + tig + 4];
            }
            #pragma unroll
            for (int in = 0; in < 8; in++) {
                int nr = wn + in * 8 + gid;
                bf[in][0] = uB[nr * 36 + ks * 8 + tig];
                bf[in][1] = uB[nr * 36 + ks * 8 + tig + 4];
            }
            #pragma unroll
            for (int im = 0; im < 2; im++)
                #pragma unroll
                for (int in = 0; in < 8; in++)
                    mma8(acc[im][in], af[im][0], af[im][1], af[im][2], af[im][3],
                         bf[in][0], bf[in][1]);
        }
        __syncthreads();
    }

    // ---- epilogue ----
    // wn=0 warps hold gates i (in 0..3) and f (in 4..7); wn=64 hold g and o.
    if (wn == 64) {     // exchange: g at sm[0..4095], o at sm[4096..8191]
        #pragma unroll
        for (int im = 0; im < 2; im++)
            #pragma unroll
            for (int in = 0; in < 4; in++) {
                int m = wm + im * 16 + gid;
                int u = in * 8 + tig * 2;
                float2 v;
                v.x = acc[im][in][0];     v.y = acc[im][in][1];
                *(float2*)&sm[m * 32 + u] = v;
                v.x = acc[im][in + 4][0]; v.y = acc[im][in + 4][1];
                *(float2*)&sm[4096 + m * 32 + u] = v;
                v.x = acc[im][in][2];     v.y = acc[im][in][3];
                *(float2*)&sm[(m + 8) * 32 + u] = v;
                v.x = acc[im][in + 4][2]; v.y = acc[im][in + 4][3];
                *(float2*)&sm[4096 + (m + 8) * 32 + u] = v;
            }
    }
    __syncthreads();
    if (wn == 0) {
        #pragma unroll
        for (int im = 0; im < 2; im++)
            #pragma unroll
            for (int in = 0; in < 4; in++)
                #pragma unroll
                for (int half = 0; half < 2; half++) {
                    int m = wm + im * 16 + gid + half * 8;
                    #pragma unroll
                    for (int du = 0; du < 2; du++) {
                        int u = in * 8 + tig * 2 + du;
                        int unit = j0 + u;
                        float gi = acc[im][in][half * 2 + du]     + bih[unit] + bhh[unit];
                        float gf = acc[im][in + 4][half * 2 + du] + bih[HH + unit] + bhh[HH + unit];
                        float gg = sm[m * 32 + u]        + bih[2 * HH + unit] + bhh[2 * HH + unit];
                        float go = sm[4096 + m * 32 + u] + bih[3 * HH + unit] + bhh[3 * HH + unit];
                        size_t off = (rowbase + m) * HH + unit;
                        float c2 = sigf(gf) * cprev[off] + sigf(gi) * tanhf(gg);
                        cout[off] = c2;
                        hout[off] = sigf(go) * tanhf(c2);
                    }
                }
    }
}

// ---------------- output linear: out[rows,128] = A[rows,1024] @ Wlin^T + b ----------------
__global__ __launch_bounds__(128) void linear_kernel(
    const float* __restrict__ A,
    const float* __restrict__ W,
    const float* __restrict__ bias,
    float* __restrict__ out)
{
    __shared__ float sml[64 * 36 * 2];
    float* sA = sml;
    float* sB = sml + 64 * 36;

    const int tid  = threadIdx.x;
    const int warp = tid >> 5, lane = tid & 31;
    const int gid  = lane >> 2, tig = lane & 3;
    const int wm   = (warp & 1) * 32;
    const int wn   = (warp >> 1) * 32;
    const int n0   = blockIdx.x * 64;
    const size_t rowbase = (size_t)blockIdx.y * 64;

    float acc[2][4][4];
    #pragma unroll
    for (int i = 0; i < 2; i++)
        #pragma unroll
        for (int j = 0; j < 4; j++)
            #pragma unroll
            for (int q = 0; q < 4; q++) acc[i][j][q] = 0.f;

    for (int k0 = 0; k0 < HH; k0 += 32) {
        #pragma unroll
        for (int i = 0; i < 4; i++) {
            int q = tid + i * 128;
            int r = q >> 3, c4 = (q & 7) << 2;
            st4tf(sA + r * 36 + c4, *(const float4*)(A + (rowbase + r) * (size_t)HH + k0 + c4));
        }
        #pragma unroll
        for (int i = 0; i < 4; i++) {
            int q = tid + i * 128;
            int r = q >> 3, c4 = (q & 7) << 2;
            st4tf(sB + r * 36 + c4, *(const float4*)(W + (size_t)(n0 + r) * HH + k0 + c4));
        }
        __syncthreads();
        const uint32_t* uA = (const uint32_t*)sA;
        const uint32_t* uB = (const uint32_t*)sB;
        #pragma unroll
        for (int ks = 0; ks < 4; ks++) {
            uint32_t af[2][4], bf[4][2];
            #pragma unroll
            for (int im = 0; im < 2; im++) {
                int mr = wm + im * 16 + gid;
                af[im][0] = uA[mr * 36 + ks * 8 + tig];
                af[im][1] = uA[(mr + 8) * 36 + ks * 8 + tig];
                af[im][2] = uA[mr * 36 + ks * 8 + tig + 4];
                af[im][3] = uA[(mr + 8) * 36 + ks * 8 + tig + 4];
            }
            #pragma unroll
            for (int in = 0; in < 4; in++) {
                int nr = wn + in * 8 + gid;
                bf[in][0] = uB[nr * 36 + ks * 8 + tig];
                bf[in][1] = uB[nr * 36 + ks * 8 + tig + 4];
            }
            #pragma unroll
            for (int im = 0; im < 2; im++)
                #pragma unroll
                for (int in = 0; in < 4; in++)
                    mma8(acc[im][in], af[im][0], af[im][1], af[im][2], af[im][3],
                         bf[in][0], bf[in][1]);
        }
        __syncthreads();
    }

    #pragma unroll
    for (int im = 0; im < 2; im++)
        #pragma unroll
        for (int in = 0; in < 4; in++) {
            int m = wm + im * 16 + gid;
            int n = wn + in * 8 + tig * 2;
            size_t r0 = rowbase + m;
            out[r0 * FF + n0 + n]           = acc[im][in][0] + bias[n0 + n];
            out[r0 * FF + n0 + n + 1]       = acc[im][in][1] + bias[n0 + n + 1];
            out[(r0 + 8) * FF + n0 + n]     = acc[im][in][2] + bias[n0 + n];
            out[(r0 + 8) * FF + n0 + n + 1] = acc[im][in][3] + bias[n0 + n + 1];
        }
}

// ---------------- init: seed states + bias-preload gate buffers ----------------
__global__ void init_states(const float* __restrict__ h0, const float* __restrict__ c0,
    const float* __restrict__ bih0, const float* __restrict__ bhh0,
    const float* __restrict__ bih1, const float* __restrict__ bhh1)
{
    int i = blockIdx.x * blockDim.x + threadIdx.x;   // grid 2048x256 = 524288
    if (i < HS_SLOT) {
        g_hs0[0][i] = h0[i];
        g_hs1[0][i] = h0[HS_SLOT + i];
        g_cs0[i]    = c0[i];
        g_cs1[i]    = c0[HS_SLOT + i];
    }
    if (i < BB * 4096) {
        int col = i & 4095;
        g_gates0[i] = bih0[col] + bhh0[col];
        g_gates1[i] = bih1[col] + bhh1[col];
    }
    if (i < 64) { g_cnt0[i] = 0; g_cnt1[i] = 0; }
}

// ---------------- output assembly ----------------
__global__ void assemble(const float* __restrict__ inMusic, float* __restrict__ out) {
    const size_t OUTM = (size_t)NS * BB * FF * NPRED;
    const size_t HFO  = OUTM;
    const size_t CFO  = HFO + 2 * (size_t)HS_SLOT;
    const size_t NSE  = CFO + 2 * (size_t)HS_SLOT;
    const size_t TOT  = NSE + PRED_SLOT;
    for (size_t idx = blockIdx.x * (size_t)blockDim.x + threadIdx.x; idx < TOT;
         idx += (size_t)gridDim.x * blockDim.x) {
        float v;
        if (idx < OUTM) {
            int n = (int)(idx & 7);
            int f = (int)((idx >> 3) & 127);
            int b = (int)((idx >> 10) & 127);
            int r = (int)(idx >> 17);
            if (r < NPRED && n >= r)
                v = inMusic[((size_t)r * BB + b) * FF + f];
            else if (r >= 2 * n + 2)
                v = g_preds[n][(size_t)(r - n - 1) * PRED_SLOT + b * FF + f];
            else
                v = 0.f;
        } else if (idx < CFO) {
            size_t i = idx - HFO;
            size_t rest = i & (HS_SLOT - 1);
            v = (i >= HS_SLOT) ? g_hs1[0][95 * (size_t)HS_SLOT + rest]
                               : g_hs0[0][95 * (size_t)HS_SLOT + rest];
        } else if (idx < NSE) {
            size_t i = idx - CFO;
            size_t rest = i & (HS_SLOT - 1);
            v = (i >= HS_SLOT) ? g_cs1[95 * (size_t)HS_SLOT + rest]
                               : g_cs0[95 * (size_t)HS_SLOT + rest];
        } else {
            v = g_preds[0][95 * (size_t)PRED_SLOT + (idx - NSE)];
        }
        out[idx] = v;
    }
}

// ---------------- host orchestration ----------------
extern "C" void kernel_launch(void* const* d_in, const int* in_sizes, int n_in,
                              void* d_out, int out_size) {
    const float* inMusic = (const float*)d_in[0];
    const float* h0   = (const float*)d_in[1];
    const float* c0   = (const float*)d_in[2];
    const float* Wih0 = (const float*)d_in[3];
    const float* Whh0 = (const float*)d_in[4];
    const float* bih0 = (const float*)d_in[5];
    const float* bhh0 = (const float*)d_in[6];
    const float* Wih1 = (const float*)d_in[7];
    const float* Whh1 = (const float*)d_in[8];
    const float* bih1 = (const float*)d_in[9];
    const float* bhh1 = (const float*)d_in[10];
    const float* Wlin = (const float*)d_in[11];
    const float* blin = (const float*)d_in[12];
    float* out = (float*)d_out;

    float *hs0, *hs1, *cs0, *cs1, *preds, *gates0, *gates1;
    int *cnt0, *cnt1;
    cudaGetSymbolAddress((void**)&hs0, g_hs0);
    cudaGetSymbolAddress((void**)&hs1, g_hs1);
    cudaGetSymbolAddress((void**)&cs0, g_cs0);
    cudaGetSymbolAddress((void**)&cs1, g_cs1);
    cudaGetSymbolAddress((void**)&preds, g_preds);
    cudaGetSymbolAddress((void**)&gates0, g_gates0);
    cudaGetSymbolAddress((void**)&gates1, g_gates1);
    cudaGetSymbolAddress((void**)&cnt0, g_cnt0);
    cudaGetSymbolAddress((void**)&cnt1, g_cnt1);
    const size_t BUF = (size_t)NS * HS_SLOT;

    const int SMEM_BIG = 9216 * 4;   // 36864
    cudaFuncSetAttribute(lstm_big, cudaFuncAttributeMaxDynamicSharedMemorySize, SMEM_BIG);

    init_states<<<2048, 256>>>(h0, c0, bih0, bhh0, bih1, bhh1);

    // --- sequential filter chain, k = 1..95 (fused split-K, 2 kernels/step) ---
    for (int k = 1; k < NS; k++) {
        lstm_chain_fused<<<dim3(64, 1, 6), 256>>>(
            inMusic + (size_t)k * PRED_SLOT, FF,
            hs0 + (size_t)(k - 1) * HS_SLOT, Wih0, Whh0,
            gates0, cnt0, 6, 6, bih0, bhh0,
            cs0 + (size_t)(k - 1) * HS_SLOT,
            hs0 + (size_t)k * HS_SLOT, cs0 + (size_t)k * HS_SLOT);
        lstm_chain_fused<<<dim3(64, 1, 8), 256>>>(
            hs0 + (size_t)k * HS_SLOT, HH,
            hs1 + (size_t)(k - 1) * HS_SLOT, Wih1, Whh1,
            gates1, cnt1, 8, 8, bih1, bhh1,
            cs1 + (size_t)(k - 1) * HS_SLOT,
            hs1 + (size_t)k * HS_SLOT, cs1 + (size_t)k * HS_SLOT);
    }

    // --- pred0 for k = 1..95 ---
    linear_kernel<<<dim3(2, 95 * 2), 128>>>(hs1 + HS_SLOT, Wlin, blin, preds + PRED_SLOT);

    // --- closed-loop prediction steps, batched across active k ---
    for (int n = 1; n < NPRED; n++) {
        int k0 = n + 1;
        int nk = 94 - 2 * n;                 // active k in [n+1, 94-n]
        int src = (n - 1) & 1, dst = n & 1;
        size_t off = (size_t)k0 * HS_SLOT;
        lstm_big<<<dim3(32, nk), 256, SMEM_BIG>>>(
            preds + (size_t)(n - 1) * NS * PRED_SLOT + (size_t)k0 * PRED_SLOT, FF,
            hs0 + src * BUF + off, Wih0, Whh0, bih0, bhh0,
            cs0 + off, hs0 + dst * BUF + off, cs0 + off);
        lstm_big<<<dim3(32, nk), 256, SMEM_BIG>>>(
            hs0 + dst * BUF + off, HH,
            hs1 + src * BUF + off, Wih1, Whh1, bih1, bhh1,
            cs1 + off, hs1 + dst * BUF + off, cs1 + off);
        linear_kernel<<<dim3(2, nk * 2), 128>>>(
            hs1 + dst * BUF + off, Wlin, blin,
            preds + (size_t)n * NS * PRED_SLOT + (size_t)k0 * PRED_SLOT);
    }

    assemble<<<4096, 256>>>(inMusic, out);
    (void)in_sizes; (void)n_in; (void)out_size;
}

// round 11
// speedup vs baseline: 1.9013x; 1.6250x over previous
#include <cuda_runtime.h>
#include <cstdint>

#define BB 128     // batch
#define HH 1024    // hidden
#define FF 128     // features
#define NS 96      // samples
#define NPRED 8    // horizon
#define HS_SLOT (BB*HH)     // 131072
#define PRED_SLOT (BB*FF)   // 16384

// ---------------- device scratch (static: no allocations allowed) ----------------
// NOTE: no cuda_fp16.h anywhere — half-precision data lives in uint16_t arrays,
// produced/consumed exclusively via inline-PTX cvt + u32 fragments.
__device__ float g_hs0[NS*HS_SLOT];              // chain h, layer0 (fp32, proven path)
__device__ float g_hs1[NS*HS_SLOT];              // chain h, layer1
__device__ __align__(16) uint16_t g_h16_0[2][NS*HS_SLOT];   // inner h (f16 bits)
__device__ __align__(16) uint16_t g_h16_1[2][NS*HS_SLOT];
__device__ float g_cs0[NS*HS_SLOT];              // c stays fp32 (shared chain+inner)
__device__ float g_cs1[NS*HS_SLOT];
__device__ float g_preds[NPRED][NS*PRED_SLOT];              // fp32 (output path)
__device__ __align__(16) uint16_t g_preds16[NPRED][NS*PRED_SLOT];  // f16 bits (GEMM in)
__device__ __align__(16) uint16_t g_w16_ih0[4096*FF];
__device__ __align__(16) uint16_t g_w16_hh0[4096*HH];
__device__ __align__(16) uint16_t g_w16_ih1[4096*HH];
__device__ __align__(16) uint16_t g_w16_hh1[4096*HH];
__device__ __align__(16) uint16_t g_w16_lin[FF*HH];
__device__ float g_gates0[BB * 4096];   // bias-preloaded gate accumulators
__device__ float g_gates1[BB * 4096];
__device__ int   g_cnt0[64];
__device__ int   g_cnt1[64];

// ---------------- helpers ----------------
__device__ __forceinline__ uint32_t f2tf(float x) {
    uint32_t r;
    asm("cvt.rna.tf32.f32 %0, %1;" : "=r"(r) : "f"(x));
    return r;
}

// pack two fp32 into f16x2 bits: lower half <- lo, upper half <- hi
__device__ __forceinline__ uint32_t pack_h2(float lo, float hi) {
    uint32_t r;
    asm("cvt.rn.f16x2.f32 %0, %1, %2;" : "=r"(r) : "f"(hi), "f"(lo));
    return r;
}

__device__ __forceinline__ void mma8(float* c, uint32_t a0, uint32_t a1, uint32_t a2,
                                     uint32_t a3, uint32_t b0, uint32_t b1) {
    asm volatile(
        "mma.sync.aligned.m16n8k8.row.col.f32.tf32.tf32.f32 "
        "{%0,%1,%2,%3},{%4,%5,%6,%7},{%8,%9},{%0,%1,%2,%3};\n"
        : "+f"(c[0]), "+f"(c[1]), "+f"(c[2]), "+f"(c[3])
        : "r"(a0), "r"(a1), "r"(a2), "r"(a3), "r"(b0), "r"(b1));
}

__device__ __forceinline__ void mma16(float* c, uint32_t a0, uint32_t a1, uint32_t a2,
                                      uint32_t a3, uint32_t b0, uint32_t b1) {
    asm volatile(
        "mma.sync.aligned.m16n8k16.row.col.f32.f16.f16.f32 "
        "{%0,%1,%2,%3},{%4,%5,%6,%7},{%8,%9},{%0,%1,%2,%3};\n"
        : "+f"(c[0]), "+f"(c[1]), "+f"(c[2]), "+f"(c[3])
        : "r"(a0), "r"(a1), "r"(a2), "r"(a3), "r"(b0), "r"(b1));
}

__device__ __forceinline__ float sigf(float x) { return 1.f / (1.f + __expf(-x)); }

__device__ __forceinline__ void st4tf(float* d, float4 v) {
    d[0] = __uint_as_float(f2tf(v.x));
    d[1] = __uint_as_float(f2tf(v.y));
    d[2] = __uint_as_float(f2tf(v.z));
    d[3] = __uint_as_float(f2tf(v.w));
}

__device__ __forceinline__ void pick_src16(int c, int nx,
    const uint16_t* Ax, int Kx, const uint16_t* Ah,
    const uint16_t* Wih, const uint16_t* Whh,
    const uint16_t*& A, const uint16_t*& W, int& K, int& k0)
{
    if (c < nx) { A = Ax; W = Wih; K = Kx; k0 = c << 5; }
    else        { A = Ah; W = Whh; K = HH; k0 = (c - nx) << 5; }
}

// =====================================================================
// Fused chain cell (fp32 tf32 — PROVEN R6 version, byte-identical logic).
// BM=128 x BN=64 per CTA, split-K over gridDim.z. grid (64, 1, SPLIT).
// =====================================================================
__global__ __launch_bounds__(256) void lstm_chain_fused(
    const float* __restrict__ Ax, int Kx,
    const float* __restrict__ Ah,
    const float* __restrict__ Wih, const float* __restrict__ Whh,
    float* __restrict__ gates, int* __restrict__ cnt,
    int nsplit, int chunksPer,
    const float* __restrict__ bih, const float* __restrict__ bhh,
    const float* __restrict__ cprev,
    float* __restrict__ hout, float* __restrict__ cout)
{
    __shared__ float sm[128 * 36 + 64 * 36];
    __shared__ int isLast;
    float* sA = sm;
    float* sB = sm + 128 * 36;

    const int tid  = threadIdx.x;
    const int warp = tid >> 5, lane = tid & 31;
    const int gid  = lane >> 2, tig = lane & 3;
    const int wm   = (warp & 3) * 32;
    const int wn   = (warp >> 2) * 32;
    const int j0   = blockIdx.x * 16;
    const int nx   = Kx >> 5;
    const int c0   = blockIdx.z * chunksPer, c1 = c0 + chunksPer;
    const int c4   = (tid & 7) << 2;
    const int rbase = tid >> 3;

    float acc[2][4][4];
    #pragma unroll
    for (int i = 0; i < 2; i++)
        #pragma unroll
        for (int j = 0; j < 4; j++)
            #pragma unroll
            for (int q = 0; q < 4; q++) acc[i][j][q] = 0.f;

    float4 pA[4], pB[2];
    auto issue = [&](int c) {
        const float *A, *W; int K, k0;
        if (c < nx) { A = Ax; W = Wih; K = Kx; k0 = c << 5; }
        else        { A = Ah; W = Whh; K = HH; k0 = (c - nx) << 5; }
        #pragma unroll
        for (int i = 0; i < 4; i++) {
            int r = rbase + i * 32;
            pA[i] = *(const float4*)(A + (size_t)r * K + k0 + c4);
        }
        #pragma unroll
        for (int i = 0; i < 2; i++) {
            int r = rbase + i * 32;
            int wr = (r >> 4) * HH + j0 + (r & 15);
            pB[i] = *(const float4*)(W + (size_t)wr * K + k0 + c4);
        }
    };

    issue(c0);
    for (int c = c0; c < c1; c++) {
        #pragma unroll
        for (int i = 0; i < 4; i++) st4tf(sA + (rbase + i * 32) * 36 + c4, pA[i]);
        #pragma unroll
        for (int i = 0; i < 2; i++) st4tf(sB + (rbase + i * 32) * 36 + c4, pB[i]);
        __syncthreads();
        if (c + 1 < c1) issue(c + 1);
        const uint32_t* uA = (const uint32_t*)sA;
        const uint32_t* uB = (const uint32_t*)sB;
        #pragma unroll
        for (int ks = 0; ks < 4; ks++) {
            uint32_t af[2][4], bf[4][2];
            #pragma unroll
            for (int im = 0; im < 2; im++) {
                int mr = wm + im * 16 + gid;
                af[im][0] = uA[mr * 36 + ks * 8 + tig];
                af[im][1] = uA[(mr + 8) * 36 + ks * 8 + tig];
                af[im][2] = uA[mr * 36 + ks * 8 + tig + 4];
                af[im][3] = uA[(mr + 8) * 36 + ks * 8 + tig + 4];
            }
            #pragma unroll
            for (int in = 0; in < 4; in++) {
                int nr = wn + in * 8 + gid;
                bf[in][0] = uB[nr * 36 + ks * 8 + tig];
                bf[in][1] = uB[nr * 36 + ks * 8 + tig + 4];
            }
            #pragma unroll
            for (int im = 0; im < 2; im++)
                #pragma unroll
                for (int in = 0; in < 4; in++)
                    mma8(acc[im][in], af[im][0], af[im][1], af[im][2], af[im][3],
                         bf[in][0], bf[in][1]);
        }
        __syncthreads();
    }

    #pragma unroll
    for (int im = 0; im < 2; im++)
        #pragma unroll
        for (int in = 0; in < 4; in++) {
            int m = wm + im * 16 + gid;
            int nl = wn + in * 8 + tig * 2;
            int gc = (nl >> 4) * HH + j0 + (nl & 15);
            atomicAdd(&gates[(size_t)m * 4096 + gc],           acc[im][in][0]);
            atomicAdd(&gates[(size_t)m * 4096 + gc + 1],       acc[im][in][1]);
            atomicAdd(&gates[(size_t)(m + 8) * 4096 + gc],     acc[im][in][2]);
            atomicAdd(&gates[(size_t)(m + 8) * 4096 + gc + 1], acc[im][in][3]);
        }

    __threadfence();
    __syncthreads();
    if (tid == 0) {
        int old = atomicAdd(cnt + blockIdx.x, 1);
        isLast = (old == nsplit - 1);
    }
    __syncthreads();

    if (isLast) {
        __threadfence();
        #pragma unroll
        for (int e = tid; e < 2048; e += 256) {
            int m = e >> 4, j = e & 15;
            int unit = j0 + j;
            float gi = __ldcg(&gates[(size_t)m * 4096 + unit]);
            float gf = __ldcg(&gates[(size_t)m * 4096 + HH + unit]);
            float gg = __ldcg(&gates[(size_t)m * 4096 + 2 * HH + unit]);
            float go = __ldcg(&gates[(size_t)m * 4096 + 3 * HH + unit]);
            float c2 = sigf(gf) * cprev[(size_t)m * HH + unit] + sigf(gi) * tanhf(gg);
            cout[(size_t)m * HH + unit] = c2;
            hout[(size_t)m * HH + unit] = sigf(go) * tanhf(c2);
            gates[(size_t)m * 4096 + unit]          = bih[unit] + bhh[unit];
            gates[(size_t)m * 4096 + HH + unit]     = bih[HH + unit] + bhh[HH + unit];
            gates[(size_t)m * 4096 + 2 * HH + unit] = bih[2 * HH + unit] + bhh[2 * HH + unit];
            gates[(size_t)m * 4096 + 3 * HH + unit] = bih[3 * HH + unit] + bhh[3 * HH + unit];
        }
        if (tid == 0) cnt[blockIdx.x] = 0;
    }
}

// =====================================================================
// Batched inner cell (f16 bits, no __half): BM=256 x BN=128, 512 threads,
// warp tile M=16 x N=128 (all 4 gates thread-local -> register epilogue).
// grid (32, nk/2).
// =====================================================================
__global__ __launch_bounds__(512) void lstm_big(
    const uint16_t* __restrict__ Ax, int Kx,
    const uint16_t* __restrict__ Ah,
    const uint16_t* __restrict__ Wih, const uint16_t* __restrict__ Whh,
    const float* __restrict__ bih, const float* __restrict__ bhh,
    const float* __restrict__ cprev,
    uint16_t* __restrict__ hout, float* __restrict__ cout)
{
    __shared__ uint32_t su[256 * 20 + 128 * 20];
    __shared__ float sBias[128];
    uint32_t* sA = su;
    uint32_t* sB = su + 256 * 20;

    const int tid  = threadIdx.x;
    const int warp = tid >> 5, lane = tid & 31;
    const int gid  = lane >> 2, tig = lane & 3;
    const int wm   = warp * 16;
    const int j0   = blockIdx.x * 32;
    const size_t rowbase = (size_t)blockIdx.y * 256;
    const int nx = Kx >> 5, C = nx + 32;
    const int lr = tid >> 2;        // 0..127
    const int lc = tid & 3;

    if (tid < 128)
        sBias[tid] = bih[(tid >> 5) * HH + j0 + (tid & 31)]
                   + bhh[(tid >> 5) * HH + j0 + (tid & 31)];

    float acc[16][4];
    #pragma unroll
    for (int i = 0; i < 16; i++)
        #pragma unroll
        for (int q = 0; q < 4; q++) acc[i][q] = 0.f;

    const uint16_t *A, *W; int K, k0;
    pick_src16(0, nx, Ax, Kx, Ah, Wih, Whh, A, W, K, k0);
    const int wr = (lr >> 5) * HH + j0 + (lr & 31);
    uint4 pA0 = *(const uint4*)(A + (rowbase + lr) * (size_t)K + k0 + lc * 8);
    uint4 pA1 = *(const uint4*)(A + (rowbase + lr + 128) * (size_t)K + k0 + lc * 8);
    uint4 pB  = *(const uint4*)(W + (size_t)wr * K + k0 + lc * 8);

    for (int c = 0; c < C; c++) {
        *(uint4*)(sA + lr * 20 + lc * 4)         = pA0;
        *(uint4*)(sA + (lr + 128) * 20 + lc * 4) = pA1;
        *(uint4*)(sB + lr * 20 + lc * 4)         = pB;
        __syncthreads();
        if (c + 1 < C) {
            pick_src16(c + 1, nx, Ax, Kx, Ah, Wih, Whh, A, W, K, k0);
            pA0 = *(const uint4*)(A + (rowbase + lr) * (size_t)K + k0 + lc * 8);
            pA1 = *(const uint4*)(A + (rowbase + lr + 128) * (size_t)K + k0 + lc * 8);
            pB  = *(const uint4*)(W + (size_t)wr * K + k0 + lc * 8);
        }
        const int mr = wm + gid;
        #pragma unroll
        for (int ks = 0; ks < 2; ks++) {
            uint32_t a0 = sA[mr * 20 + ks * 8 + tig];
            uint32_t a1 = sA[(mr + 8) * 20 + ks * 8 + tig];
            uint32_t a2 = sA[mr * 20 + ks * 8 + 4 + tig];
            uint32_t a3 = sA[(mr + 8) * 20 + ks * 8 + 4 + tig];
            #pragma unroll
            for (int in = 0; in < 16; in++) {
                int nr = in * 8 + gid;
                uint32_t b0 = sB[nr * 20 + ks * 8 + tig];
                uint32_t b1 = sB[nr * 20 + ks * 8 + 4 + tig];
                mma16(acc[in], a0, a1, a2, a3, b0, b1);
            }
        }
        __syncthreads();
    }

    // ---- register-local LSTM epilogue (paired stores: float2 c, packed-u32 h) ----
    #pragma unroll
    for (int in = 0; in < 4; in++)
        #pragma unroll
        for (int half = 0; half < 2; half++) {
            int q0 = half * 2;                    // q0 -> col u0, q0+1 -> col u0+1
            int u0 = in * 8 + 2 * tig;
            int m  = wm + gid + half * 8;
            size_t off = (rowbase + m) * HH + j0 + u0;   // even
            float2 cp = *(const float2*)(cprev + off);
            float gi0 = acc[in][q0]          + sBias[u0];
            float gf0 = acc[in + 4][q0]      + sBias[32 + u0];
            float gg0 = acc[in + 8][q0]      + sBias[64 + u0];
            float go0 = acc[in + 12][q0]     + sBias[96 + u0];
            float gi1 = acc[in][q0 + 1]      + sBias[u0 + 1];
            float gf1 = acc[in + 4][q0 + 1]  + sBias[32 + u0 + 1];
            float gg1 = acc[in + 8][q0 + 1]  + sBias[64 + u0 + 1];
            float go1 = acc[in + 12][q0 + 1] + sBias[96 + u0 + 1];
            float c2a = sigf(gf0) * cp.x + sigf(gi0) * tanhf(gg0);
            float c2b = sigf(gf1) * cp.y + sigf(gi1) * tanhf(gg1);
            float h2a = sigf(go0) * tanhf(c2a);
            float h2b = sigf(go1) * tanhf(c2b);
            float2 cv; cv.x = c2a; cv.y = c2b;
            *(float2*)(cout + off) = cv;
            *(uint32_t*)(hout + off) = pack_h2(h2a, h2b);
        }
}

// =====================================================================
// Linear (f16 bits): out[rows,128] = A[rows,1024] @ W^T + b. grid (2, rows/64).
// =====================================================================
__global__ __launch_bounds__(128) void linear_kernel(
    const uint16_t* __restrict__ A,
    const uint16_t* __restrict__ W,
    const float* __restrict__ bias,
    float* __restrict__ out, uint16_t* __restrict__ out16)
{
    __shared__ uint32_t su[64 * 20 * 2];
    uint32_t* sA = su;
    uint32_t* sB = su + 64 * 20;

    const int tid  = threadIdx.x;
    const int warp = tid >> 5, lane = tid & 31;
    const int gid  = lane >> 2, tig = lane & 3;
    const int wm   = warp * 16;
    const int n0   = blockIdx.x * 64;
    const size_t rowbase = (size_t)blockIdx.y * 64;
    const int lr = tid >> 2;   // 0..31
    const int lc = tid & 3;

    float acc[8][4];
    #pragma unroll
    for (int i = 0; i < 8; i++)
        #pragma unroll
        for (int q = 0; q < 4; q++) acc[i][q] = 0.f;

    for (int k0 = 0; k0 < HH; k0 += 32) {
        *(uint4*)(sA + lr * 20 + lc * 4) =
            *(const uint4*)(A + (rowbase + lr) * (size_t)HH + k0 + lc * 8);
        *(uint4*)(sA + (lr + 32) * 20 + lc * 4) =
            *(const uint4*)(A + (rowbase + lr + 32) * (size_t)HH + k0 + lc * 8);
        *(uint4*)(sB + lr * 20 + lc * 4) =
            *(const uint4*)(W + (size_t)(n0 + lr) * HH + k0 + lc * 8);
        *(uint4*)(sB + (lr + 32) * 20 + lc * 4) =
            *(const uint4*)(W + (size_t)(n0 + lr + 32) * HH + k0 + lc * 8);
        __syncthreads();
        const int mr = wm + gid;
        #pragma unroll
        for (int ks = 0; ks < 2; ks++) {
            uint32_t a0 = sA[mr * 20 + ks * 8 + tig];
            uint32_t a1 = sA[(mr + 8) * 20 + ks * 8 + tig];
            uint32_t a2 = sA[mr * 20 + ks * 8 + 4 + tig];
            uint32_t a3 = sA[(mr + 8) * 20 + ks * 8 + 4 + tig];
            #pragma unroll
            for (int in = 0; in < 8; in++) {
                int nr = in * 8 + gid;
                uint32_t b0 = sB[nr * 20 + ks * 8 + tig];
                uint32_t b1 = sB[nr * 20 + ks * 8 + 4 + tig];
                mma16(acc[in], a0, a1, a2, a3, b0, b1);
            }
        }
        __syncthreads();
    }

    #pragma unroll
    for (int in = 0; in < 8; in++)
        #pragma unroll
        for (int half = 0; half < 2; half++) {
            int q0 = half * 2;
            int n  = n0 + in * 8 + 2 * tig;       // even
            int m  = wm + gid + half * 8;
            size_t row = rowbase + m;
            float va = acc[in][q0]     + bias[n];
            float vb = acc[in][q0 + 1] + bias[n + 1];
            float2 v; v.x = va; v.y = vb;
            *(float2*)(out + row * FF + n) = v;
            *(uint32_t*)(out16 + row * FF + n) = pack_h2(va, vb);
        }
}

// ---------------- fp32 -> f16-bits convert (paired) ----------------
__global__ void f2h_kernel(const float* __restrict__ src, uint32_t* __restrict__ dst,
                           int npairs) {
    for (int i = blockIdx.x * blockDim.x + threadIdx.x; i < npairs;
         i += gridDim.x * blockDim.x)
        dst[i] = pack_h2(src[2 * i], src[2 * i + 1]);
}

// ---------------- init: seed states + bias-preload gate buffers ----------------
__global__ void init_states(const float* __restrict__ h0, const float* __restrict__ c0,
    const float* __restrict__ bih0, const float* __restrict__ bhh0,
    const float* __restrict__ bih1, const float* __restrict__ bhh1)
{
    int i = blockIdx.x * blockDim.x + threadIdx.x;   // grid 2048x256
    if (i < HS_SLOT) {
        g_hs0[i] = h0[i];
        g_hs1[i] = h0[HS_SLOT + i];
        g_cs0[i] = c0[i];
        g_cs1[i] = c0[HS_SLOT + i];
    }
    if (i < BB * 4096) {
        int col = i & 4095;
        g_gates0[i] = bih0[col] + bhh0[col];
        g_gates1[i] = bih1[col] + bhh1[col];
    }
    if (i < 64) { g_cnt0[i] = 0; g_cnt1[i] = 0; }
}

// ---------------- output assembly ----------------
__global__ void assemble(const float* __restrict__ inMusic, float* __restrict__ out) {
    const size_t OUTM = (size_t)NS * BB * FF * NPRED;
    const size_t HFO  = OUTM;
    const size_t CFO  = HFO + 2 * (size_t)HS_SLOT;
    const size_t NSE  = CFO + 2 * (size_t)HS_SLOT;
    const size_t TOT  = NSE + PRED_SLOT;
    for (size_t idx = blockIdx.x * (size_t)blockDim.x + threadIdx.x; idx < TOT;
         idx += (size_t)gridDim.x * blockDim.x) {
        float v;
        if (idx < OUTM) {
            int n = (int)(idx & 7);
            int f = (int)((idx >> 3) & 127);
            int b = (int)((idx >> 10) & 127);
            int r = (int)(idx >> 17);
            if (r < NPRED && n >= r)
                v = inMusic[((size_t)r * BB + b) * FF + f];
            else if (r >= 2 * n + 2)
                v = g_preds[n][(size_t)(r - n - 1) * PRED_SLOT + b * FF + f];
            else
                v = 0.f;
        } else if (idx < CFO) {
            size_t i = idx - HFO;
            size_t rest = i & (HS_SLOT - 1);
            v = (i >= HS_SLOT) ? g_hs1[95 * (size_t)HS_SLOT + rest]
                               : g_hs0[95 * (size_t)HS_SLOT + rest];
        } else if (idx < NSE) {
            size_t i = idx - CFO;
            size_t rest = i & (HS_SLOT - 1);
            v = (i >= HS_SLOT) ? g_cs1[95 * (size_t)HS_SLOT + rest]
                               : g_cs0[95 * (size_t)HS_SLOT + rest];
        } else {
            v = g_preds[0][95 * (size_t)PRED_SLOT + (idx - NSE)];
        }
        out[idx] = v;
    }
}

// ---------------- host orchestration ----------------
extern "C" void kernel_launch(void* const* d_in, const int* in_sizes, int n_in,
                              void* d_out, int out_size) {
    const float* inMusic = (const float*)d_in[0];
    const float* h0   = (const float*)d_in[1];
    const float* c0   = (const float*)d_in[2];
    const float* Wih0 = (const float*)d_in[3];
    const float* Whh0 = (const float*)d_in[4];
    const float* bih0 = (const float*)d_in[5];
    const float* bhh0 = (const float*)d_in[6];
    const float* Wih1 = (const float*)d_in[7];
    const float* Whh1 = (const float*)d_in[8];
    const float* bih1 = (const float*)d_in[9];
    const float* bhh1 = (const float*)d_in[10];
    const float* Wlin = (const float*)d_in[11];
    const float* blin = (const float*)d_in[12];
    float* out = (float*)d_out;

    float *hs0, *hs1, *cs0, *cs1, *preds, *gates0, *gates1;
    uint16_t *h16_0, *h16_1, *preds16, *w_ih0, *w_hh0, *w_ih1, *w_hh1, *w_lin;
    int *cnt0, *cnt1;
    cudaGetSymbolAddress((void**)&hs0, g_hs0);
    cudaGetSymbolAddress((void**)&hs1, g_hs1);
    cudaGetSymbolAddress((void**)&h16_0, g_h16_0);
    cudaGetSymbolAddress((void**)&h16_1, g_h16_1);
    cudaGetSymbolAddress((void**)&cs0, g_cs0);
    cudaGetSymbolAddress((void**)&cs1, g_cs1);
    cudaGetSymbolAddress((void**)&preds, g_preds);
    cudaGetSymbolAddress((void**)&preds16, g_preds16);
    cudaGetSymbolAddress((void**)&w_ih0, g_w16_ih0);
    cudaGetSymbolAddress((void**)&w_hh0, g_w16_hh0);
    cudaGetSymbolAddress((void**)&w_ih1, g_w16_ih1);
    cudaGetSymbolAddress((void**)&w_hh1, g_w16_hh1);
    cudaGetSymbolAddress((void**)&w_lin, g_w16_lin);
    cudaGetSymbolAddress((void**)&gates0, g_gates0);
    cudaGetSymbolAddress((void**)&gates1, g_gates1);
    cudaGetSymbolAddress((void**)&cnt0, g_cnt0);
    cudaGetSymbolAddress((void**)&cnt1, g_cnt1);
    const size_t BUF = (size_t)NS * HS_SLOT;

    // --- weight conversions to f16 bits (deterministic each call) ---
    f2h_kernel<<<256, 256>>>(Wih0, (uint32_t*)w_ih0, 4096 * FF / 2);
    f2h_kernel<<<2048, 256>>>(Whh0, (uint32_t*)w_hh0, 4096 * HH / 2);
    f2h_kernel<<<2048, 256>>>(Wih1, (uint32_t*)w_ih1, 4096 * HH / 2);
    f2h_kernel<<<2048, 256>>>(Whh1, (uint32_t*)w_hh1, 4096 * HH / 2);
    f2h_kernel<<<256, 256>>>(Wlin, (uint32_t*)w_lin, FF * HH / 2);
    init_states<<<2048, 256>>>(h0, c0, bih0, bhh0, bih1, bhh1);

    // --- sequential filter chain, k = 1..95 (fp32 split-K fused, proven) ---
    for (int k = 1; k < NS; k++) {
        lstm_chain_fused<<<dim3(64, 1, 6), 256>>>(
            inMusic + (size_t)k * PRED_SLOT, FF,
            hs0 + (size_t)(k - 1) * HS_SLOT, Wih0, Whh0,
            gates0, cnt0, 6, 6, bih0, bhh0,
            cs0 + (size_t)(k - 1) * HS_SLOT,
            hs0 + (size_t)k * HS_SLOT, cs0 + (size_t)k * HS_SLOT);
        lstm_chain_fused<<<dim3(64, 1, 8), 256>>>(
            hs0 + (size_t)k * HS_SLOT, HH,
            hs1 + (size_t)(k - 1) * HS_SLOT, Wih1, Whh1,
            gates1, cnt1, 8, 8, bih1, bhh1,
            cs1 + (size_t)(k - 1) * HS_SLOT,
            hs1 + (size_t)k * HS_SLOT, cs1 + (size_t)k * HS_SLOT);
    }

    // --- bridge chain h to f16 buffers (buffer 0) ---
    f2h_kernel<<<4096, 256>>>(hs0, (uint32_t*)h16_0, NS * HS_SLOT / 2);
    f2h_kernel<<<4096, 256>>>(hs1, (uint32_t*)h16_1, NS * HS_SLOT / 2);

    // --- pred0 for k = 1..95 ---
    linear_kernel<<<dim3(2, 95 * 2), 128>>>(h16_1 + HS_SLOT, w_lin, blin,
                                            preds + PRED_SLOT, preds16 + PRED_SLOT);

    // --- closed-loop prediction steps, batched across active k ---
    for (int n = 1; n < NPRED; n++) {
        int k0 = n + 1;
        int nk = 94 - 2 * n;                 // even: 92..80
        int src = (n - 1) & 1, dst = n & 1;
        size_t off = (size_t)k0 * HS_SLOT;
        lstm_big<<<dim3(32, nk / 2), 512>>>(
            preds16 + (size_t)(n - 1) * NS * PRED_SLOT + (size_t)k0 * PRED_SLOT, FF,
            h16_0 + src * BUF + off, w_ih0, w_hh0, bih0, bhh0,
            cs0 + off, h16_0 + dst * BUF + off, cs0 + off);
        lstm_big<<<dim3(32, nk / 2), 512>>>(
            h16_0 + dst * BUF + off, HH,
            h16_1 + src * BUF + off, w_ih1, w_hh1, bih1, bhh1,
            cs1 + off, h16_1 + dst * BUF + off, cs1 + off);
        linear_kernel<<<dim3(2, nk * 2), 128>>>(
            h16_1 + dst * BUF + off, w_lin, blin,
            preds + (size_t)n * NS * PRED_SLOT + (size_t)k0 * PRED_SLOT,
            preds16 + (size_t)n * NS * PRED_SLOT + (size_t)k0 * PRED_SLOT);
    }

    assemble<<<4096, 256>>>(inMusic, out);
    (void)in_sizes; (void)n_in; (void)out_size;
}

// round 12
// speedup vs baseline: 2.1073x; 1.1083x over previous
#include <cuda_runtime.h>
#include <cstdint>

#define BB 128     // batch
#define HH 1024    // hidden
#define FF 128     // features
#define NS 96      // samples
#define NPRED 8    // horizon
#define HS_SLOT (BB*HH)     // 131072
#define PRED_SLOT (BB*FF)   // 16384

// ---------------- device scratch (static: no allocations allowed) ----------------
// No cuda_fp16.h anywhere — half data lives in uint16_t arrays via PTX cvt.
__device__ __align__(16) uint16_t g_h16_0[2][NS*HS_SLOT];   // h layer0 (f16 bits)
__device__ __align__(16) uint16_t g_h16_1[2][NS*HS_SLOT];   // h layer1
__device__ float g_cs0[NS*HS_SLOT];              // c stays fp32
__device__ float g_cs1[NS*HS_SLOT];
__device__ float g_preds[NPRED][NS*PRED_SLOT];              // fp32 (output path)
__device__ __align__(16) uint16_t g_preds16[NPRED][NS*PRED_SLOT];  // f16 bits
__device__ __align__(16) uint16_t g_in16[NS*PRED_SLOT];
__device__ __align__(16) uint16_t g_w16_ih0[4096*FF];
__device__ __align__(16) uint16_t g_w16_hh0[4096*HH];
__device__ __align__(16) uint16_t g_w16_ih1[4096*HH];
__device__ __align__(16) uint16_t g_w16_hh1[4096*HH];
__device__ __align__(16) uint16_t g_w16_lin[FF*HH];
__device__ float g_gates0[BB * 4096];   // bias-preloaded gate accumulators
__device__ float g_gates1[BB * 4096];
__device__ int   g_cnt0[64];
__device__ int   g_cnt1[64];

// ---------------- helpers ----------------
// pack two fp32 into f16x2 bits: lower half <- lo, upper half <- hi
__device__ __forceinline__ uint32_t pack_h2(float lo, float hi) {
    uint32_t r;
    asm("cvt.rn.f16x2.f32 %0, %1, %2;" : "=r"(r) : "f"(hi), "f"(lo));
    return r;
}

__device__ __forceinline__ uint16_t f2h1(float x) {
    uint16_t r;
    asm("cvt.rn.f16.f32 %0, %1;" : "=h"(r) : "f"(x));
    return r;
}

__device__ __forceinline__ float h2f(uint16_t b) {
    float f;
    asm("{ .reg .b16 h; mov.b16 h, %1; cvt.f32.f16 %0, h; }" : "=f"(f) : "h"(b));
    return f;
}

__device__ __forceinline__ void mma16(float* c, uint32_t a0, uint32_t a1, uint32_t a2,
                                      uint32_t a3, uint32_t b0, uint32_t b1) {
    asm volatile(
        "mma.sync.aligned.m16n8k16.row.col.f32.f16.f16.f32 "
        "{%0,%1,%2,%3},{%4,%5,%6,%7},{%8,%9},{%0,%1,%2,%3};\n"
        : "+f"(c[0]), "+f"(c[1]), "+f"(c[2]), "+f"(c[3])
        : "r"(a0), "r"(a1), "r"(a2), "r"(a3), "r"(b0), "r"(b1));
}

__device__ __forceinline__ float sigf(float x) { return 1.f / (1.f + __expf(-x)); }

__device__ __forceinline__ void pick_src16(int c, int nx, int shift,
    const uint16_t* Ax, int Kx, const uint16_t* Ah,
    const uint16_t* Wih, const uint16_t* Whh,
    const uint16_t*& A, const uint16_t*& W, int& K, int& k0)
{
    if (c < nx) { A = Ax; W = Wih; K = Kx; k0 = c << shift; }
    else        { A = Ah; W = Whh; K = HH; k0 = (c - nx) << shift; }
}

// =====================================================================
// Fused chain cell (f16 bits): BM=128 x BN=64, 64-wide K chunks,
// split-K over gridDim.z. 256 threads = 8 warps, warp tile M=16 x N=64.
// grid (64, 1, SPLIT).
// =====================================================================
__global__ __launch_bounds__(256) void lstm_chain_fused16(
    const uint16_t* __restrict__ Ax, int Kx,
    const uint16_t* __restrict__ Ah,
    const uint16_t* __restrict__ Wih, const uint16_t* __restrict__ Whh,
    float* __restrict__ gates, int* __restrict__ cnt,
    int nsplit, int chunksPer,
    const float* __restrict__ bih, const float* __restrict__ bhh,
    const float* __restrict__ cprev,
    uint16_t* __restrict__ hout, float* __restrict__ cout)
{
    __shared__ uint32_t su[128 * 36 + 64 * 36];   // 64 halves/row = 32 u32 + 4 pad
    __shared__ int isLast;
    uint32_t* sA = su;
    uint32_t* sB = su + 128 * 36;

    const int tid  = threadIdx.x;
    const int warp = tid >> 5, lane = tid & 31;
    const int gid  = lane >> 2, tig = lane & 3;
    const int wm   = warp * 16;
    const int j0   = blockIdx.x * 16;
    const int nx   = Kx >> 6;                    // 64-wide chunks
    const int c0   = blockIdx.z * chunksPer, c1 = c0 + chunksPer;

    float acc[8][4];
    #pragma unroll
    for (int i = 0; i < 8; i++)
        #pragma unroll
        for (int q = 0; q < 4; q++) acc[i][q] = 0.f;

    uint4 pA[4], pB[2];
    auto issue = [&](int c) {
        const uint16_t *A, *W; int K, k0;
        pick_src16(c, nx, 6, Ax, Kx, Ah, Wih, Whh, A, W, K, k0);
        #pragma unroll
        for (int i = 0; i < 4; i++) {
            int q = tid + (i << 8);
            int r = q >> 3, c8 = q & 7;
            pA[i] = *(const uint4*)(A + (size_t)r * K + k0 + c8 * 8);
        }
        #pragma unroll
        for (int i = 0; i < 2; i++) {
            int q = tid + (i << 8);
            int r = q >> 3, c8 = q & 7;
            int wr = (r >> 4) * HH + j0 + (r & 15);
            pB[i] = *(const uint4*)(W + (size_t)wr * K + k0 + c8 * 8);
        }
    };

    issue(c0);
    for (int c = c0; c < c1; c++) {
        #pragma unroll
        for (int i = 0; i < 4; i++) {
            int q = tid + (i << 8);
            int r = q >> 3, c8 = q & 7;
            *(uint4*)(sA + r * 36 + c8 * 4) = pA[i];
        }
        #pragma unroll
        for (int i = 0; i < 2; i++) {
            int q = tid + (i << 8);
            int r = q >> 3, c8 = q & 7;
            *(uint4*)(sB + r * 36 + c8 * 4) = pB[i];
        }
        __syncthreads();
        if (c + 1 < c1) issue(c + 1);
        const int mr = wm + gid;
        #pragma unroll
        for (int ks = 0; ks < 4; ks++) {
            uint32_t a0 = sA[mr * 36 + ks * 8 + tig];
            uint32_t a1 = sA[(mr + 8) * 36 + ks * 8 + tig];
            uint32_t a2 = sA[mr * 36 + ks * 8 + 4 + tig];
            uint32_t a3 = sA[(mr + 8) * 36 + ks * 8 + 4 + tig];
            #pragma unroll
            for (int in = 0; in < 8; in++) {
                int nr = in * 8 + gid;
                uint32_t b0 = sB[nr * 36 + ks * 8 + tig];
                uint32_t b1 = sB[nr * 36 + ks * 8 + 4 + tig];
                mma16(acc[in], a0, a1, a2, a3, b0, b1);
            }
        }
        __syncthreads();
    }

    // ---- accumulate partial gates ----
    {
        const int m = wm + gid;
        #pragma unroll
        for (int in = 0; in < 8; in++) {
            int nl = in * 8 + 2 * tig;
            int gc = (nl >> 4) * HH + j0 + (nl & 15);
            atomicAdd(&gates[(size_t)m * 4096 + gc],           acc[in][0]);
            atomicAdd(&gates[(size_t)m * 4096 + gc + 1],       acc[in][1]);
            atomicAdd(&gates[(size_t)(m + 8) * 4096 + gc],     acc[in][2]);
            atomicAdd(&gates[(size_t)(m + 8) * 4096 + gc + 1], acc[in][3]);
        }
    }

    __threadfence();
    __syncthreads();
    if (tid == 0) {
        int old = atomicAdd(cnt + blockIdx.x, 1);
        isLast = (old == nsplit - 1);
    }
    __syncthreads();

    if (isLast) {
        __threadfence();
        #pragma unroll
        for (int e = tid; e < 2048; e += 256) {       // 128 rows x 16 units
            int m = e >> 4, j = e & 15;
            int unit = j0 + j;
            float gi = __ldcg(&gates[(size_t)m * 4096 + unit]);
            float gf = __ldcg(&gates[(size_t)m * 4096 + HH + unit]);
            float gg = __ldcg(&gates[(size_t)m * 4096 + 2 * HH + unit]);
            float go = __ldcg(&gates[(size_t)m * 4096 + 3 * HH + unit]);
            float c2 = sigf(gf) * cprev[(size_t)m * HH + unit] + sigf(gi) * tanhf(gg);
            cout[(size_t)m * HH + unit] = c2;
            hout[(size_t)m * HH + unit] = f2h1(sigf(go) * tanhf(c2));
            gates[(size_t)m * 4096 + unit]          = bih[unit] + bhh[unit];
            gates[(size_t)m * 4096 + HH + unit]     = bih[HH + unit] + bhh[HH + unit];
            gates[(size_t)m * 4096 + 2 * HH + unit] = bih[2 * HH + unit] + bhh[2 * HH + unit];
            gates[(size_t)m * 4096 + 3 * HH + unit] = bih[3 * HH + unit] + bhh[3 * HH + unit];
        }
        if (tid == 0) cnt[blockIdx.x] = 0;
    }
}

// =====================================================================
// Batched inner cell (f16 bits — PROVEN R11): BM=256 x BN=128, 512 threads.
// grid (32, nk/2).
// =====================================================================
__global__ __launch_bounds__(512) void lstm_big(
    const uint16_t* __restrict__ Ax, int Kx,
    const uint16_t* __restrict__ Ah,
    const uint16_t* __restrict__ Wih, const uint16_t* __restrict__ Whh,
    const float* __restrict__ bih, const float* __restrict__ bhh,
    const float* __restrict__ cprev,
    uint16_t* __restrict__ hout, float* __restrict__ cout)
{
    __shared__ uint32_t su[256 * 20 + 128 * 20];
    __shared__ float sBias[128];
    uint32_t* sA = su;
    uint32_t* sB = su + 256 * 20;

    const int tid  = threadIdx.x;
    const int warp = tid >> 5, lane = tid & 31;
    const int gid  = lane >> 2, tig = lane & 3;
    const int wm   = warp * 16;
    const int j0   = blockIdx.x * 32;
    const size_t rowbase = (size_t)blockIdx.y * 256;
    const int nx = Kx >> 5, C = nx + 32;
    const int lr = tid >> 2;        // 0..127
    const int lc = tid & 3;

    if (tid < 128)
        sBias[tid] = bih[(tid >> 5) * HH + j0 + (tid & 31)]
                   + bhh[(tid >> 5) * HH + j0 + (tid & 31)];

    float acc[16][4];
    #pragma unroll
    for (int i = 0; i < 16; i++)
        #pragma unroll
        for (int q = 0; q < 4; q++) acc[i][q] = 0.f;

    const uint16_t *A, *W; int K, k0;
    pick_src16(0, nx, 5, Ax, Kx, Ah, Wih, Whh, A, W, K, k0);
    const int wr = (lr >> 5) * HH + j0 + (lr & 31);
    uint4 pA0 = *(const uint4*)(A + (rowbase + lr) * (size_t)K + k0 + lc * 8);
    uint4 pA1 = *(const uint4*)(A + (rowbase + lr + 128) * (size_t)K + k0 + lc * 8);
    uint4 pB  = *(const uint4*)(W + (size_t)wr * K + k0 + lc * 8);

    for (int c = 0; c < C; c++) {
        *(uint4*)(sA + lr * 20 + lc * 4)         = pA0;
        *(uint4*)(sA + (lr + 128) * 20 + lc * 4) = pA1;
        *(uint4*)(sB + lr * 20 + lc * 4)         = pB;
        __syncthreads();
        if (c + 1 < C) {
            pick_src16(c + 1, nx, 5, Ax, Kx, Ah, Wih, Whh, A, W, K, k0);
            pA0 = *(const uint4*)(A + (rowbase + lr) * (size_t)K + k0 + lc * 8);
            pA1 = *(const uint4*)(A + (rowbase + lr + 128) * (size_t)K + k0 + lc * 8);
            pB  = *(const uint4*)(W + (size_t)wr * K + k0 + lc * 8);
        }
        const int mr = wm + gid;
        #pragma unroll
        for (int ks = 0; ks < 2; ks++) {
            uint32_t a0 = sA[mr * 20 + ks * 8 + tig];
            uint32_t a1 = sA[(mr + 8) * 20 + ks * 8 + tig];
            uint32_t a2 = sA[mr * 20 + ks * 8 + 4 + tig];
            uint32_t a3 = sA[(mr + 8) * 20 + ks * 8 + 4 + tig];
            #pragma unroll
            for (int in = 0; in < 16; in++) {
                int nr = in * 8 + gid;
                uint32_t b0 = sB[nr * 20 + ks * 8 + tig];
                uint32_t b1 = sB[nr * 20 + ks * 8 + 4 + tig];
                mma16(acc[in], a0, a1, a2, a3, b0, b1);
            }
        }
        __syncthreads();
    }

    // ---- register-local LSTM epilogue ----
    #pragma unroll
    for (int in = 0; in < 4; in++)
        #pragma unroll
        for (int half = 0; half < 2; half++) {
            int q0 = half * 2;
            int u0 = in * 8 + 2 * tig;
            int m  = wm + gid + half * 8;
            size_t off = (rowbase + m) * HH + j0 + u0;
            float2 cp = *(const float2*)(cprev + off);
            float gi0 = acc[in][q0]          + sBias[u0];
            float gf0 = acc[in + 4][q0]      + sBias[32 + u0];
            float gg0 = acc[in + 8][q0]      + sBias[64 + u0];
            float go0 = acc[in + 12][q0]     + sBias[96 + u0];
            float gi1 = acc[in][q0 + 1]      + sBias[u0 + 1];
            float gf1 = acc[in + 4][q0 + 1]  + sBias[32 + u0 + 1];
            float gg1 = acc[in + 8][q0 + 1]  + sBias[64 + u0 + 1];
            float go1 = acc[in + 12][q0 + 1] + sBias[96 + u0 + 1];
            float c2a = sigf(gf0) * cp.x + sigf(gi0) * tanhf(gg0);
            float c2b = sigf(gf1) * cp.y + sigf(gi1) * tanhf(gg1);
            float h2a = sigf(go0) * tanhf(c2a);
            float h2b = sigf(go1) * tanhf(c2b);
            float2 cv; cv.x = c2a; cv.y = c2b;
            *(float2*)(cout + off) = cv;
            *(uint32_t*)(hout + off) = pack_h2(h2a, h2b);
        }
}

// =====================================================================
// Linear (f16 bits — PROVEN R11): out[rows,128] = A @ W^T + b. grid (2, rows/64).
// =====================================================================
__global__ __launch_bounds__(128) void linear_kernel(
    const uint16_t* __restrict__ A,
    const uint16_t* __restrict__ W,
    const float* __restrict__ bias,
    float* __restrict__ out, uint16_t* __restrict__ out16)
{
    __shared__ uint32_t su[64 * 20 * 2];
    uint32_t* sA = su;
    uint32_t* sB = su + 64 * 20;

    const int tid  = threadIdx.x;
    const int warp = tid >> 5, lane = tid & 31;
    const int gid  = lane >> 2, tig = lane & 3;
    const int wm   = warp * 16;
    const int n0   = blockIdx.x * 64;
    const size_t rowbase = (size_t)blockIdx.y * 64;
    const int lr = tid >> 2;   // 0..31
    const int lc = tid & 3;

    float acc[8][4];
    #pragma unroll
    for (int i = 0; i < 8; i++)
        #pragma unroll
        for (int q = 0; q < 4; q++) acc[i][q] = 0.f;

    for (int k0 = 0; k0 < HH; k0 += 32) {
        *(uint4*)(sA + lr * 20 + lc * 4) =
            *(const uint4*)(A + (rowbase + lr) * (size_t)HH + k0 + lc * 8);
        *(uint4*)(sA + (lr + 32) * 20 + lc * 4) =
            *(const uint4*)(A + (rowbase + lr + 32) * (size_t)HH + k0 + lc * 8);
        *(uint4*)(sB + lr * 20 + lc * 4) =
            *(const uint4*)(W + (size_t)(n0 + lr) * HH + k0 + lc * 8);
        *(uint4*)(sB + (lr + 32) * 20 + lc * 4) =
            *(const uint4*)(W + (size_t)(n0 + lr + 32) * HH + k0 + lc * 8);
        __syncthreads();
        const int mr = wm + gid;
        #pragma unroll
        for (int ks = 0; ks < 2; ks++) {
            uint32_t a0 = sA[mr * 20 + ks * 8 + tig];
            uint32_t a1 = sA[(mr + 8) * 20 + ks * 8 + tig];
            uint32_t a2 = sA[mr * 20 + ks * 8 + 4 + tig];
            uint32_t a3 = sA[(mr + 8) * 20 + ks * 8 + 4 + tig];
            #pragma unroll
            for (int in = 0; in < 8; in++) {
                int nr = in * 8 + gid;
                uint32_t b0 = sB[nr * 20 + ks * 8 + tig];
                uint32_t b1 = sB[nr * 20 + ks * 8 + 4 + tig];
                mma16(acc[in], a0, a1, a2, a3, b0, b1);
            }
        }
        __syncthreads();
    }

    #pragma unroll
    for (int in = 0; in < 8; in++)
        #pragma unroll
        for (int half = 0; half < 2; half++) {
            int q0 = half * 2;
            int n  = n0 + in * 8 + 2 * tig;
            int m  = wm + gid + half * 8;
            size_t row = rowbase + m;
            float va = acc[in][q0]     + bias[n];
            float vb = acc[in][q0 + 1] + bias[n + 1];
            float2 v; v.x = va; v.y = vb;
            *(float2*)(out + row * FF + n) = v;
            *(uint32_t*)(out16 + row * FF + n) = pack_h2(va, vb);
        }
}

// ---------------- fp32 -> f16-bits convert (paired) ----------------
__global__ void f2h_kernel(const float* __restrict__ src, uint32_t* __restrict__ dst,
                           int npairs) {
    for (int i = blockIdx.x * blockDim.x + threadIdx.x; i < npairs;
         i += gridDim.x * blockDim.x)
        dst[i] = pack_h2(src[2 * i], src[2 * i + 1]);
}

// ---------------- init: seed states + bias-preload gate buffers ----------------
__global__ void init_states(const float* __restrict__ h0, const float* __restrict__ c0,
    const float* __restrict__ bih0, const float* __restrict__ bhh0,
    const float* __restrict__ bih1, const float* __restrict__ bhh1)
{
    int i = blockIdx.x * blockDim.x + threadIdx.x;   // grid 2048x256
    if (i < HS_SLOT) {
        g_h16_0[0][i] = f2h1(h0[i]);
        g_h16_1[0][i] = f2h1(h0[HS_SLOT + i]);
        g_cs0[i] = c0[i];
        g_cs1[i] = c0[HS_SLOT + i];
    }
    if (i < BB * 4096) {
        int col = i & 4095;
        g_gates0[i] = bih0[col] + bhh0[col];
        g_gates1[i] = bih1[col] + bhh1[col];
    }
    if (i < 64) { g_cnt0[i] = 0; g_cnt1[i] = 0; }
}

// ---------------- output assembly ----------------
__global__ void assemble(const float* __restrict__ inMusic, float* __restrict__ out) {
    const size_t OUTM = (size_t)NS * BB * FF * NPRED;
    const size_t HFO  = OUTM;
    const size_t CFO  = HFO + 2 * (size_t)HS_SLOT;
    const size_t NSE  = CFO + 2 * (size_t)HS_SLOT;
    const size_t TOT  = NSE + PRED_SLOT;
    for (size_t idx = blockIdx.x * (size_t)blockDim.x + threadIdx.x; idx < TOT;
         idx += (size_t)gridDim.x * blockDim.x) {
        float v;
        if (idx < OUTM) {
            int n = (int)(idx & 7);
            int f = (int)((idx >> 3) & 127);
            int b = (int)((idx >> 10) & 127);
            int r = (int)(idx >> 17);
            if (r < NPRED && n >= r)
                v = inMusic[((size_t)r * BB + b) * FF + f];
            else if (r >= 2 * n + 2)
                v = g_preds[n][(size_t)(r - n - 1) * PRED_SLOT + b * FF + f];
            else
                v = 0.f;
        } else if (idx < CFO) {
            size_t i = idx - HFO;
            size_t rest = i & (HS_SLOT - 1);
            v = (i >= HS_SLOT) ? h2f(g_h16_1[0][95 * (size_t)HS_SLOT + rest])
                               : h2f(g_h16_0[0][95 * (size_t)HS_SLOT + rest]);
        } else if (idx < NSE) {
            size_t i = idx - CFO;
            size_t rest = i & (HS_SLOT - 1);
            v = (i >= HS_SLOT) ? g_cs1[95 * (size_t)HS_SLOT + rest]
                               : g_cs0[95 * (size_t)HS_SLOT + rest];
        } else {
            v = g_preds[0][95 * (size_t)PRED_SLOT + (idx - NSE)];
        }
        out[idx] = v;
    }
}

// ---------------- host orchestration ----------------
extern "C" void kernel_launch(void* const* d_in, const int* in_sizes, int n_in,
                              void* d_out, int out_size) {
    const float* inMusic = (const float*)d_in[0];
    const float* h0   = (const float*)d_in[1];
    const float* c0   = (const float*)d_in[2];
    const float* Wih0 = (const float*)d_in[3];
    const float* Whh0 = (const float*)d_in[4];
    const float* bih0 = (const float*)d_in[5];
    const float* bhh0 = (const float*)d_in[6];
    const float* Wih1 = (const float*)d_in[7];
    const float* Whh1 = (const float*)d_in[8];
    const float* bih1 = (const float*)d_in[9];
    const float* bhh1 = (const float*)d_in[10];
    const float* Wlin = (const float*)d_in[11];
    const float* blin = (const float*)d_in[12];
    float* out = (float*)d_out;

    float *cs0, *cs1, *preds, *gates0, *gates1;
    uint16_t *h16_0, *h16_1, *preds16, *in16, *w_ih0, *w_hh0, *w_ih1, *w_hh1, *w_lin;
    int *cnt0, *cnt1;
    cudaGetSymbolAddress((void**)&h16_0, g_h16_0);
    cudaGetSymbolAddress((void**)&h16_1, g_h16_1);
    cudaGetSymbolAddress((void**)&cs0, g_cs0);
    cudaGetSymbolAddress((void**)&cs1, g_cs1);
    cudaGetSymbolAddress((void**)&preds, g_preds);
    cudaGetSymbolAddress((void**)&preds16, g_preds16);
    cudaGetSymbolAddress((void**)&in16, g_in16);
    cudaGetSymbolAddress((void**)&w_ih0, g_w16_ih0);
    cudaGetSymbolAddress((void**)&w_hh0, g_w16_hh0);
    cudaGetSymbolAddress((void**)&w_ih1, g_w16_ih1);
    cudaGetSymbolAddress((void**)&w_hh1, g_w16_hh1);
    cudaGetSymbolAddress((void**)&w_lin, g_w16_lin);
    cudaGetSymbolAddress((void**)&gates0, g_gates0);
    cudaGetSymbolAddress((void**)&gates1, g_gates1);
    cudaGetSymbolAddress((void**)&cnt0, g_cnt0);
    cudaGetSymbolAddress((void**)&cnt1, g_cnt1);
    const size_t BUF = (size_t)NS * HS_SLOT;

    // --- conversions to f16 bits (deterministic each call) ---
    f2h_kernel<<<256, 256>>>(Wih0, (uint32_t*)w_ih0, 4096 * FF / 2);
    f2h_kernel<<<2048, 256>>>(Whh0, (uint32_t*)w_hh0, 4096 * HH / 2);
    f2h_kernel<<<2048, 256>>>(Wih1, (uint32_t*)w_ih1, 4096 * HH / 2);
    f2h_kernel<<<2048, 256>>>(Whh1, (uint32_t*)w_hh1, 4096 * HH / 2);
    f2h_kernel<<<256, 256>>>(Wlin, (uint32_t*)w_lin, FF * HH / 2);
    f2h_kernel<<<1024, 256>>>(inMusic, (uint32_t*)in16, NS * PRED_SLOT / 2);
    init_states<<<2048, 256>>>(h0, c0, bih0, bhh0, bih1, bhh1);

    // --- sequential filter chain, k = 1..95 (f16 split-K fused) ---
    for (int k = 1; k < NS; k++) {
        lstm_chain_fused16<<<dim3(64, 1, 6), 256>>>(
            in16 + (size_t)k * PRED_SLOT, FF,
            h16_0 + (size_t)(k - 1) * HS_SLOT, w_ih0, w_hh0,
            gates0, cnt0, 6, 3, bih0, bhh0,
            cs0 + (size_t)(k - 1) * HS_SLOT,
            h16_0 + (size_t)k * HS_SLOT, cs0 + (size_t)k * HS_SLOT);
        lstm_chain_fused16<<<dim3(64, 1, 8), 256>>>(
            h16_0 + (size_t)k * HS_SLOT, HH,
            h16_1 + (size_t)(k - 1) * HS_SLOT, w_ih1, w_hh1,
            gates1, cnt1, 8, 4, bih1, bhh1,
            cs1 + (size_t)(k - 1) * HS_SLOT,
            h16_1 + (size_t)k * HS_SLOT, cs1 + (size_t)k * HS_SLOT);
    }

    // --- pred0 for k = 1..95 ---
    linear_kernel<<<dim3(2, 95 * 2), 128>>>(h16_1 + HS_SLOT, w_lin, blin,
                                            preds + PRED_SLOT, preds16 + PRED_SLOT);

    // --- closed-loop prediction steps, batched across active k ---
    for (int n = 1; n < NPRED; n++) {
        int k0 = n + 1;
        int nk = 94 - 2 * n;                 // even: 92..80
        int src = (n - 1) & 1, dst = n & 1;
        size_t off = (size_t)k0 * HS_SLOT;
        lstm_big<<<dim3(32, nk / 2), 512>>>(
            preds16 + (size_t)(n - 1) * NS * PRED_SLOT + (size_t)k0 * PRED_SLOT, FF,
            h16_0 + src * BUF + off, w_ih0, w_hh0, bih0, bhh0,
            cs0 + off, h16_0 + dst * BUF + off, cs0 + off);
        lstm_big<<<dim3(32, nk / 2), 512>>>(
            h16_0 + dst * BUF + off, HH,
            h16_1 + src * BUF + off, w_ih1, w_hh1, bih1, bhh1,
            cs1 + off, h16_1 + dst * BUF + off, cs1 + off);
        linear_kernel<<<dim3(2, nk * 2), 128>>>(
            h16_1 + dst * BUF + off, w_lin, blin,
            preds + (size_t)n * NS * PRED_SLOT + (size_t)k0 * PRED_SLOT,
            preds16 + (size_t)n * NS * PRED_SLOT + (size_t)k0 * PRED_SLOT);
    }

    assemble<<<4096, 256>>>(inMusic, out);
    (void)in_sizes; (void)n_in; (void)out_size;
}

// round 16
// speedup vs baseline: 2.3055x; 1.0941x over previous
#include <cuda_runtime.h>
#include <cstdint>

#define BB 128     // batch
#define HH 1024    // hidden
#define FF 128     // features
#define NS 96      // samples
#define NPRED 8    // horizon
#define HS_SLOT (BB*HH)     // 131072
#define PRED_SLOT (BB*FF)   // 16384
#define NCTA 256            // persistent chain grid (co-resident: 2/SM x 148 = 296 >= 256)

// ---------------- device scratch (static: no allocations allowed) ----------------
// No cuda_fp16.h anywhere — half data lives in uint16_t arrays via PTX cvt.
__device__ __align__(16) uint16_t g_h16_0[2][NS*HS_SLOT];   // h layer0 (f16 bits)
__device__ __align__(16) uint16_t g_h16_1[2][NS*HS_SLOT];   // h layer1
__device__ float g_cs0[NS*HS_SLOT];              // c stays fp32
__device__ float g_cs1[NS*HS_SLOT];
__device__ float g_preds[NPRED][NS*PRED_SLOT];              // fp32 (output path)
__device__ __align__(16) uint16_t g_preds16[NPRED][NS*PRED_SLOT];  // f16 bits
__device__ __align__(16) uint16_t g_in16[NS*PRED_SLOT];
__device__ __align__(16) uint16_t g_w16_ih0[4096*FF];
__device__ __align__(16) uint16_t g_w16_hh0[4096*HH];
__device__ __align__(16) uint16_t g_w16_ih1[4096*HH];
__device__ __align__(16) uint16_t g_w16_hh1[4096*HH];
__device__ __align__(16) uint16_t g_w16_lin[FF*HH];
__device__ float g_gates0[BB * 4096];   // bias-preloaded gate accumulators
__device__ float g_gates1[BB * 4096];
__device__ float g_bsum0[4096];         // bih+bhh per gate-col (re-arm source)
__device__ float g_bsum1[4096];
__device__ int   g_bar;                 // persistent-kernel grid barrier
__device__ int   g_gen;

// ---------------- helpers ----------------
__device__ __forceinline__ uint32_t pack_h2(float lo, float hi) {
    uint32_t r;
    asm("cvt.rn.f16x2.f32 %0, %1, %2;" : "=r"(r) : "f"(hi), "f"(lo));
    return r;
}

__device__ __forceinline__ uint16_t f2h1(float x) {
    uint16_t r;
    asm("cvt.rn.f16.f32 %0, %1;" : "=h"(r) : "f"(x));
    return r;
}

__device__ __forceinline__ float h2f(uint16_t b) {
    float f;
    asm("{ .reg .b16 h; mov.b16 h, %1; cvt.f32.f16 %0, h; }" : "=f"(f) : "h"(b));
    return f;
}

__device__ __forceinline__ void mma16(float* c, uint32_t a0, uint32_t a1, uint32_t a2,
                                      uint32_t a3, uint32_t b0, uint32_t b1) {
    asm volatile(
        "mma.sync.aligned.m16n8k16.row.col.f32.f16.f16.f32 "
        "{%0,%1,%2,%3},{%4,%5,%6,%7},{%8,%9},{%0,%1,%2,%3};\n"
        : "+f"(c[0]), "+f"(c[1]), "+f"(c[2]), "+f"(c[3])
        : "r"(a0), "r"(a1), "r"(a2), "r"(a3), "r"(b0), "r"(b1));
}

__device__ __forceinline__ float sigf(float x) { return 1.f / (1.f + __expf(-x)); }

__device__ __forceinline__ void pick_src16(int c, int nx, int shift,
    const uint16_t* Ax, int Kx, const uint16_t* Ah,
    const uint16_t* Wih, const uint16_t* Whh,
    const uint16_t*& A, const uint16_t*& W, int& K, int& k0)
{
    if (c < nx) { A = Ax; W = Wih; K = Kx; k0 = c << shift; }
    else        { A = Ah; W = Whh; K = HH; k0 = (c - nx) << shift; }
}

// grid-wide barrier for the persistent chain kernel (all NCTA CTAs resident)
__device__ __forceinline__ void grid_barrier(int tid) {
    __syncthreads();
    if (tid == 0) {
        __threadfence();
        volatile int* genp = &g_gen;
        int g = *genp;
        if (atomicAdd(&g_bar, 1) == NCTA - 1) {
            g_bar = 0;
            __threadfence();
            atomicAdd(&g_gen, 1);
        } else {
            while (*genp == g) __nanosleep(64);
        }
        __threadfence();
    }
    __syncthreads();
}

// =====================================================================
// Chain GEMM phase (f16 bits, proven R12 tile): BM=128 x BN=64 per CTA,
// 64-wide K chunks strided over 4 splits. 256 threads, warp tile 16x64.
// =====================================================================
__device__ __forceinline__ void chain_gemm16(
    const uint16_t* __restrict__ Ax, int Kx,
    const uint16_t* __restrict__ Ah,
    const uint16_t* __restrict__ Wih, const uint16_t* __restrict__ Whh,
    float* __restrict__ gates, int jblk, int split,
    uint32_t* sA, uint32_t* sB, int tid)
{
    const int warp = tid >> 5, lane = tid & 31;
    const int gid  = lane >> 2, tig = lane & 3;
    const int wm   = warp * 16;
    const int j0   = jblk * 16;
    const int nx   = Kx >> 6;
    const int nch  = nx + 16;          // + HH/64

    float acc[8][4];
    #pragma unroll
    for (int i = 0; i < 8; i++)
        #pragma unroll
        for (int q = 0; q < 4; q++) acc[i][q] = 0.f;

    uint4 pA[4], pB[2];
    auto issue = [&](int c) {
        const uint16_t *A, *W; int K, k0;
        pick_src16(c, nx, 6, Ax, Kx, Ah, Wih, Whh, A, W, K, k0);
        #pragma unroll
        for (int i = 0; i < 4; i++) {
            int q = tid + (i << 8);
            int r = q >> 3, c8 = q & 7;
            pA[i] = *(const uint4*)(A + (size_t)r * K + k0 + c8 * 8);
        }
        #pragma unroll
        for (int i = 0; i < 2; i++) {
            int q = tid + (i << 8);
            int r = q >> 3, c8 = q & 7;
            int wr = (r >> 4) * HH + j0 + (r & 15);
            pB[i] = *(const uint4*)(W + (size_t)wr * K + k0 + c8 * 8);
        }
    };

    issue(split);
    for (int c = split; c < nch; c += 4) {
        #pragma unroll
        for (int i = 0; i < 4; i++) {
            int q = tid + (i << 8);
            int r = q >> 3, c8 = q & 7;
            *(uint4*)(sA + r * 36 + c8 * 4) = pA[i];
        }
        #pragma unroll
        for (int i = 0; i < 2; i++) {
            int q = tid + (i << 8);
            int r = q >> 3, c8 = q & 7;
            *(uint4*)(sB + r * 36 + c8 * 4) = pB[i];
        }
        __syncthreads();
        if (c + 4 < nch) issue(c + 4);
        const int mr = wm + gid;
        #pragma unroll
        for (int ks = 0; ks < 4; ks++) {
            uint32_t a0 = sA[mr * 36 + ks * 8 + tig];
            uint32_t a1 = sA[(mr + 8) * 36 + ks * 8 + tig];
            uint32_t a2 = sA[mr * 36 + ks * 8 + 4 + tig];
            uint32_t a3 = sA[(mr + 8) * 36 + ks * 8 + 4 + tig];
            #pragma unroll
            for (int in = 0; in < 8; in++) {
                int nr = in * 8 + gid;
                uint32_t b0 = sB[nr * 36 + ks * 8 + tig];
                uint32_t b1 = sB[nr * 36 + ks * 8 + 4 + tig];
                mma16(acc[in], a0, a1, a2, a3, b0, b1);
            }
        }
        __syncthreads();
    }

    // accumulate partial gates into bias-preloaded buffer
    const int m = wm + gid;
    #pragma unroll
    for (int in = 0; in < 8; in++) {
        int nl = in * 8 + 2 * tig;
        int gc = (nl >> 4) * HH + j0 + (nl & 15);
        atomicAdd(&gates[(size_t)m * 4096 + gc],           acc[in][0]);
        atomicAdd(&gates[(size_t)m * 4096 + gc + 1],       acc[in][1]);
        atomicAdd(&gates[(size_t)(m + 8) * 4096 + gc],     acc[in][2]);
        atomicAdd(&gates[(size_t)(m + 8) * 4096 + gc + 1], acc[in][3]);
    }
}

// distributed LSTM epilogue: 65536 threads x 2 elements, re-arms gate buffer
__device__ __forceinline__ void chain_epi(
    float* __restrict__ gates, const float* __restrict__ bsum,
    const float* __restrict__ cprev,
    uint16_t* __restrict__ hout, float* __restrict__ cout, int gtid)
{
    #pragma unroll
    for (int it = 0; it < 2; it++) {
        int e = gtid + it * (NCTA * 256);     // < 131072
        int m = e >> 10, u = e & 1023;
        size_t gb = (size_t)m * 4096;
        float gi = __ldcg(&gates[gb + u]);
        float gf = __ldcg(&gates[gb + HH + u]);
        float gg = __ldcg(&gates[gb + 2 * HH + u]);
        float go = __ldcg(&gates[gb + 3 * HH + u]);
        float c2 = sigf(gf) * cprev[e] + sigf(gi) * tanhf(gg);
        cout[e] = c2;
        hout[e] = f2h1(sigf(go) * tanhf(c2));
        gates[gb + u]          = bsum[u];
        gates[gb + HH + u]     = bsum[HH + u];
        gates[gb + 2 * HH + u] = bsum[2 * HH + u];
        gates[gb + 3 * HH + u] = bsum[3 * HH + u];
    }
}

// =====================================================================
// Persistent chain kernel: all 95 steps x 2 layers in ONE launch.
// grid 256 CTAs x 256 threads, guaranteed co-resident.
// =====================================================================
__global__ __launch_bounds__(256, 2) void lstm_chain_persistent(
    const uint16_t* __restrict__ in16,
    uint16_t* __restrict__ h16_0, uint16_t* __restrict__ h16_1,
    const uint16_t* __restrict__ w_ih0, const uint16_t* __restrict__ w_hh0,
    const uint16_t* __restrict__ w_ih1, const uint16_t* __restrict__ w_hh1,
    float* __restrict__ gates0, float* __restrict__ gates1,
    float* __restrict__ cs0, float* __restrict__ cs1)
{
    __shared__ uint32_t su[128 * 36 + 64 * 36];
    uint32_t* sA = su;
    uint32_t* sB = su + 128 * 36;

    const int tid   = threadIdx.x;
    const int jblk  = blockIdx.x & 63;
    const int split = blockIdx.x >> 6;
    const int gtid  = blockIdx.x * 256 + tid;

    for (int k = 1; k < NS; k++) {
        chain_gemm16(in16 + (size_t)k * PRED_SLOT, FF,
                     h16_0 + (size_t)(k - 1) * HS_SLOT,
                     w_ih0, w_hh0, gates0, jblk, split, sA, sB, tid);
        grid_barrier(tid);
        chain_epi(gates0, g_bsum0, cs0 + (size_t)(k - 1) * HS_SLOT,
                  h16_0 + (size_t)k * HS_SLOT, cs0 + (size_t)k * HS_SLOT, gtid);
        grid_barrier(tid);
        chain_gemm16(h16_0 + (size_t)k * HS_SLOT, HH,
                     h16_1 + (size_t)(k - 1) * HS_SLOT,
                     w_ih1, w_hh1, gates1, jblk, split, sA, sB, tid);
        grid_barrier(tid);
        chain_epi(gates1, g_bsum1, cs1 + (size_t)(k - 1) * HS_SLOT,
                  h16_1 + (size_t)k * HS_SLOT, cs1 + (size_t)k * HS_SLOT, gtid);
        grid_barrier(tid);
    }
}

// =====================================================================
// Batched inner cell (f16 bits — PROVEN R11/R12): BM=256 x BN=128, 512 threads.
// grid (32, nk/2).
// =====================================================================
__global__ __launch_bounds__(512) void lstm_big(
    const uint16_t* __restrict__ Ax, int Kx,
    const uint16_t* __restrict__ Ah,
    const uint16_t* __restrict__ Wih, const uint16_t* __restrict__ Whh,
    const float* __restrict__ bih, const float* __restrict__ bhh,
    const float* __restrict__ cprev,
    uint16_t* __restrict__ hout, float* __restrict__ cout)
{
    __shared__ uint32_t su[256 * 20 + 128 * 20];
    __shared__ float sBias[128];
    uint32_t* sA = su;
    uint32_t* sB = su + 256 * 20;

    const int tid  = threadIdx.x;
    const int warp = tid >> 5, lane = tid & 31;
    const int gid  = lane >> 2, tig = lane & 3;
    const int wm   = warp * 16;
    const int j0   = blockIdx.x * 32;
    const size_t rowbase = (size_t)blockIdx.y * 256;
    const int nx = Kx >> 5, C = nx + 32;
    const int lr = tid >> 2;        // 0..127
    const int lc = tid & 3;

    if (tid < 128)
        sBias[tid] = bih[(tid >> 5) * HH + j0 + (tid & 31)]
                   + bhh[(tid >> 5) * HH + j0 + (tid & 31)];

    float acc[16][4];
    #pragma unroll
    for (int i = 0; i < 16; i++)
        #pragma unroll
        for (int q = 0; q < 4; q++) acc[i][q] = 0.f;

    const uint16_t *A, *W; int K, k0;
    pick_src16(0, nx, 5, Ax, Kx, Ah, Wih, Whh, A, W, K, k0);
    const int wr = (lr >> 5) * HH + j0 + (lr & 31);
    uint4 pA0 = *(const uint4*)(A + (rowbase + lr) * (size_t)K + k0 + lc * 8);
    uint4 pA1 = *(const uint4*)(A + (rowbase + lr + 128) * (size_t)K + k0 + lc * 8);
    uint4 pB  = *(const uint4*)(W + (size_t)wr * K + k0 + lc * 8);

    for (int c = 0; c < C; c++) {
        *(uint4*)(sA + lr * 20 + lc * 4)         = pA0;
        *(uint4*)(sA + (lr + 128) * 20 + lc * 4) = pA1;
        *(uint4*)(sB + lr * 20 + lc * 4)         = pB;
        __syncthreads();
        if (c + 1 < C) {
            pick_src16(c + 1, nx, 5, Ax, Kx, Ah, Wih, Whh, A, W, K, k0);
            pA0 = *(const uint4*)(A + (rowbase + lr) * (size_t)K + k0 + lc * 8);
            pA1 = *(const uint4*)(A + (rowbase + lr + 128) * (size_t)K + k0 + lc * 8);
            pB  = *(const uint4*)(W + (size_t)wr * K + k0 + lc * 8);
        }
        const int mr = wm + gid;
        #pragma unroll
        for (int ks = 0; ks < 2; ks++) {
            uint32_t a0 = sA[mr * 20 + ks * 8 + tig];
            uint32_t a1 = sA[(mr + 8) * 20 + ks * 8 + tig];
            uint32_t a2 = sA[mr * 20 + ks * 8 + 4 + tig];
            uint32_t a3 = sA[(mr + 8) * 20 + ks * 8 + 4 + tig];
            #pragma unroll
            for (int in = 0; in < 16; in++) {
                int nr = in * 8 + gid;
                uint32_t b0 = sB[nr * 20 + ks * 8 + tig];
                uint32_t b1 = sB[nr * 20 + ks * 8 + 4 + tig];
                mma16(acc[in], a0, a1, a2, a3, b0, b1);
            }
        }
        __syncthreads();
    }

    // ---- register-local LSTM epilogue ----
    #pragma unroll
    for (int in = 0; in < 4; in++)
        #pragma unroll
        for (int half = 0; half < 2; half++) {
            int q0 = half * 2;
            int u0 = in * 8 + 2 * tig;
            int m  = wm + gid + half * 8;
            size_t off = (rowbase + m) * HH + j0 + u0;
            float2 cp = *(const float2*)(cprev + off);
            float gi0 = acc[in][q0]          + sBias[u0];
            float gf0 = acc[in + 4][q0]      + sBias[32 + u0];
            float gg0 = acc[in + 8][q0]      + sBias[64 + u0];
            float go0 = acc[in + 12][q0]     + sBias[96 + u0];
            float gi1 = acc[in][q0 + 1]      + sBias[u0 + 1];
            float gf1 = acc[in + 4][q0 + 1]  + sBias[32 + u0 + 1];
            float gg1 = acc[in + 8][q0 + 1]  + sBias[64 + u0 + 1];
            float go1 = acc[in + 12][q0 + 1] + sBias[96 + u0 + 1];
            float c2a = sigf(gf0) * cp.x + sigf(gi0) * tanhf(gg0);
            float c2b = sigf(gf1) * cp.y + sigf(gi1) * tanhf(gg1);
            float h2a = sigf(go0) * tanhf(c2a);
            float h2b = sigf(go1) * tanhf(c2b);
            float2 cv; cv.x = c2a; cv.y = c2b;
            *(float2*)(cout + off) = cv;
            *(uint32_t*)(hout + off) = pack_h2(h2a, h2b);
        }
}

// =====================================================================
// Linear (f16 bits — PROVEN R11/R12): out[rows,128] = A @ W^T + b. grid (2, rows/64).
// =====================================================================
__global__ __launch_bounds__(128) void linear_kernel(
    const uint16_t* __restrict__ A,
    const uint16_t* __restrict__ W,
    const float* __restrict__ bias,
    float* __restrict__ out, uint16_t* __restrict__ out16)
{
    __shared__ uint32_t su[64 * 20 * 2];
    uint32_t* sA = su;
    uint32_t* sB = su + 64 * 20;

    const int tid  = threadIdx.x;
    const int warp = tid >> 5, lane = tid & 31;
    const int gid  = lane >> 2, tig = lane & 3;
    const int wm   = warp * 16;
    const int n0   = blockIdx.x * 64;
    const size_t rowbase = (size_t)blockIdx.y * 64;
    const int lr = tid >> 2;   // 0..31
    const int lc = tid & 3;

    float acc[8][4];
    #pragma unroll
    for (int i = 0; i < 8; i++)
        #pragma unroll
        for (int q = 0; q < 4; q++) acc[i][q] = 0.f;

    for (int k0 = 0; k0 < HH; k0 += 32) {
        *(uint4*)(sA + lr * 20 + lc * 4) =
            *(const uint4*)(A + (rowbase + lr) * (size_t)HH + k0 + lc * 8);
        *(uint4*)(sA + (lr + 32) * 20 + lc * 4) =
            *(const uint4*)(A + (rowbase + lr + 32) * (size_t)HH + k0 + lc * 8);
        *(uint4*)(sB + lr * 20 + lc * 4) =
            *(const uint4*)(W + (size_t)(n0 + lr) * HH + k0 + lc * 8);
        *(uint4*)(sB + (lr + 32) * 20 + lc * 4) =
            *(const uint4*)(W + (size_t)(n0 + lr + 32) * HH + k0 + lc * 8);
        __syncthreads();
        const int mr = wm + gid;
        #pragma unroll
        for (int ks = 0; ks < 2; ks++) {
            uint32_t a0 = sA[mr * 20 + ks * 8 + tig];
            uint32_t a1 = sA[(mr + 8) * 20 + ks * 8 + tig];
            uint32_t a2 = sA[mr * 20 + ks * 8 + 4 + tig];
            uint32_t a3 = sA[(mr + 8) * 20 + ks * 8 + 4 + tig];
            #pragma unroll
            for (int in = 0; in < 8; in++) {
                int nr = in * 8 + gid;
                uint32_t b0 = sB[nr * 20 + ks * 8 + tig];
                uint32_t b1 = sB[nr * 20 + ks * 8 + 4 + tig];
                mma16(acc[in], a0, a1, a2, a3, b0, b1);
            }
        }
        __syncthreads();
    }

    #pragma unroll
    for (int in = 0; in < 8; in++)
        #pragma unroll
        for (int half = 0; half < 2; half++) {
            int q0 = half * 2;
            int n  = n0 + in * 8 + 2 * tig;
            int m  = wm + gid + half * 8;
            size_t row = rowbase + m;
            float va = acc[in][q0]     + bias[n];
            float vb = acc[in][q0 + 1] + bias[n + 1];
            float2 v; v.x = va; v.y = vb;
            *(float2*)(out + row * FF + n) = v;
            *(uint32_t*)(out16 + row * FF + n) = pack_h2(va, vb);
        }
}

// ---------------- fp32 -> f16-bits convert (paired) ----------------
__global__ void f2h_kernel(const float* __restrict__ src, uint32_t* __restrict__ dst,
                           int npairs) {
    for (int i = blockIdx.x * blockDim.x + threadIdx.x; i < npairs;
         i += gridDim.x * blockDim.x)
        dst[i] = pack_h2(src[2 * i], src[2 * i + 1]);
}

// ---------------- init: seed states, bias sums, gate buffers, barrier ----------------
__global__ void init_states(const float* __restrict__ h0, const float* __restrict__ c0,
    const float* __restrict__ bih0, const float* __restrict__ bhh0,
    const float* __restrict__ bih1, const float* __restrict__ bhh1)
{
    int i = blockIdx.x * blockDim.x + threadIdx.x;   // grid 2048x256
    if (i < HS_SLOT) {
        g_h16_0[0][i] = f2h1(h0[i]);
        g_h16_1[0][i] = f2h1(h0[HS_SLOT + i]);
        g_cs0[i] = c0[i];
        g_cs1[i] = c0[HS_SLOT + i];
    }
    if (i < BB * 4096) {
        int col = i & 4095;
        g_gates0[i] = bih0[col] + bhh0[col];
        g_gates1[i] = bih1[col] + bhh1[col];
    }
    if (i < 4096) {
        g_bsum0[i] = bih0[i] + bhh0[i];
        g_bsum1[i] = bih1[i] + bhh1[i];
    }
    if (i == 0) { g_bar = 0; g_gen = 0; }
}

// ---------------- output assembly ----------------
__global__ void assemble(const float* __restrict__ inMusic, float* __restrict__ out) {
    const size_t OUTM = (size_t)NS * BB * FF * NPRED;
    const size_t HFO  = OUTM;
    const size_t CFO  = HFO + 2 * (size_t)HS_SLOT;
    const size_t NSE  = CFO + 2 * (size_t)HS_SLOT;
    const size_t TOT  = NSE + PRED_SLOT;
    for (size_t idx = blockIdx.x * (size_t)blockDim.x + threadIdx.x; idx < TOT;
         idx += (size_t)gridDim.x * blockDim.x) {
        float v;
        if (idx < OUTM) {
            int n = (int)(idx & 7);
            int f = (int)((idx >> 3) & 127);
            int b = (int)((idx >> 10) & 127);
            int r = (int)(idx >> 17);
            if (r < NPRED && n >= r)
                v = inMusic[((size_t)r * BB + b) * FF + f];
            else if (r >= 2 * n + 2)
                v = g_preds[n][(size_t)(r - n - 1) * PRED_SLOT + b * FF + f];
            else
                v = 0.f;
        } else if (idx < CFO) {
            size_t i = idx - HFO;
            size_t rest = i & (HS_SLOT - 1);
            v = (i >= HS_SLOT) ? h2f(g_h16_1[0][95 * (size_t)HS_SLOT + rest])
                               : h2f(g_h16_0[0][95 * (size_t)HS_SLOT + rest]);
        } else if (idx < NSE) {
            size_t i = idx - CFO;
            size_t rest = i & (HS_SLOT - 1);
            v = (i >= HS_SLOT) ? g_cs1[95 * (size_t)HS_SLOT + rest]
                               : g_cs0[95 * (size_t)HS_SLOT + rest];
        } else {
            v = g_preds[0][95 * (size_t)PRED_SLOT + (idx - NSE)];
        }
        out[idx] = v;
    }
}

// ---------------- host orchestration ----------------
extern "C" void kernel_launch(void* const* d_in, const int* in_sizes, int n_in,
                              void* d_out, int out_size) {
    const float* inMusic = (const float*)d_in[0];
    const float* h0   = (const float*)d_in[1];
    const float* c0   = (const float*)d_in[2];
    const float* Wih0 = (const float*)d_in[3];
    const float* Whh0 = (const float*)d_in[4];
    const float* bih0 = (const float*)d_in[5];
    const float* bhh0 = (const float*)d_in[6];
    const float* Wih1 = (const float*)d_in[7];
    const float* Whh1 = (const float*)d_in[8];
    const float* bih1 = (const float*)d_in[9];
    const float* bhh1 = (const float*)d_in[10];
    const float* Wlin = (const float*)d_in[11];
    const float* blin = (const float*)d_in[12];
    float* out = (float*)d_out;

    float *cs0, *cs1, *preds, *gates0, *gates1;
    uint16_t *h16_0, *h16_1, *preds16, *in16, *w_ih0, *w_hh0, *w_ih1, *w_hh1, *w_lin;
    cudaGetSymbolAddress((void**)&h16_0, g_h16_0);
    cudaGetSymbolAddress((void**)&h16_1, g_h16_1);
    cudaGetSymbolAddress((void**)&cs0, g_cs0);
    cudaGetSymbolAddress((void**)&cs1, g_cs1);
    cudaGetSymbolAddress((void**)&preds, g_preds);
    cudaGetSymbolAddress((void**)&preds16, g_preds16);
    cudaGetSymbolAddress((void**)&in16, g_in16);
    cudaGetSymbolAddress((void**)&w_ih0, g_w16_ih0);
    cudaGetSymbolAddress((void**)&w_hh0, g_w16_hh0);
    cudaGetSymbolAddress((void**)&w_ih1, g_w16_ih1);
    cudaGetSymbolAddress((void**)&w_hh1, g_w16_hh1);
    cudaGetSymbolAddress((void**)&w_lin, g_w16_lin);
    cudaGetSymbolAddress((void**)&gates0, g_gates0);
    cudaGetSymbolAddress((void**)&gates1, g_gates1);
    const size_t BUF = (size_t)NS * HS_SLOT;

    // --- conversions to f16 bits (deterministic each call) ---
    f2h_kernel<<<256, 256>>>(Wih0, (uint32_t*)w_ih0, 4096 * FF / 2);
    f2h_kernel<<<2048, 256>>>(Whh0, (uint32_t*)w_hh0, 4096 * HH / 2);
    f2h_kernel<<<2048, 256>>>(Wih1, (uint32_t*)w_ih1, 4096 * HH / 2);
    f2h_kernel<<<2048, 256>>>(Whh1, (uint32_t*)w_hh1, 4096 * HH / 2);
    f2h_kernel<<<256, 256>>>(Wlin, (uint32_t*)w_lin, FF * HH / 2);
    f2h_kernel<<<1024, 256>>>(inMusic, (uint32_t*)in16, NS * PRED_SLOT / 2);
    init_states<<<2048, 256>>>(h0, c0, bih0, bhh0, bih1, bhh1);

    // --- entire sequential filter chain in ONE persistent launch ---
    lstm_chain_persistent<<<NCTA, 256>>>(
        in16, h16_0, h16_1, w_ih0, w_hh0, w_ih1, w_hh1,
        gates0, gates1, cs0, cs1);

    // --- pred0 for k = 1..95 ---
    linear_kernel<<<dim3(2, 95 * 2), 128>>>(h16_1 + HS_SLOT, w_lin, blin,
                                            preds + PRED_SLOT, preds16 + PRED_SLOT);

    // --- closed-loop prediction steps, batched across active k ---
    for (int n = 1; n < NPRED; n++) {
        int k0 = n + 1;
        int nk = 94 - 2 * n;                 // even: 92..80
        int src = (n - 1) & 1, dst = n & 1;
        size_t off = (size_t)k0 * HS_SLOT;
        lstm_big<<<dim3(32, nk / 2), 512>>>(
            preds16 + (size_t)(n - 1) * NS * PRED_SLOT + (size_t)k0 * PRED_SLOT, FF,
            h16_0 + src * BUF + off, w_ih0, w_hh0, bih0, bhh0,
            cs0 + off, h16_0 + dst * BUF + off, cs0 + off);
        lstm_big<<<dim3(32, nk / 2), 512>>>(
            h16_0 + dst * BUF + off, HH,
            h16_1 + src * BUF + off, w_ih1, w_hh1, bih1, bhh1,
            cs1 + off, h16_1 + dst * BUF + off, cs1 + off);
        linear_kernel<<<dim3(2, nk * 2), 128>>>(
            h16_1 + dst * BUF + off, w_lin, blin,
            preds + (size_t)n * NS * PRED_SLOT + (size_t)k0 * PRED_SLOT,
            preds16 + (size_t)n * NS * PRED_SLOT + (size_t)k0 * PRED_SLOT);
    }

    assemble<<<4096, 256>>>(inMusic, out);
    (void)in_sizes; (void)n_in; (void)out_size;
}

// round 17
// speedup vs baseline: 2.4097x; 1.0452x over previous
#include <cuda_runtime.h>
#include <cstdint>

#define BB 128     // batch
#define HH 1024    // hidden
#define FF 128     // features
#define NS 96      // samples
#define NPRED 8    // horizon
#define HS_SLOT (BB*HH)     // 131072
#define PRED_SLOT (BB*FF)   // 16384
#define NCTA 256            // persistent chain grid (co-resident: 2/SM x 148 = 296 >= 256)

// ---------------- device scratch (static: no allocations allowed) ----------------
// No cuda_fp16.h anywhere — half data lives in uint16_t arrays via PTX cvt.
__device__ __align__(16) uint16_t g_h16_0[2][NS*HS_SLOT];   // h layer0 (f16 bits)
__device__ __align__(16) uint16_t g_h16_1[2][NS*HS_SLOT];   // h layer1
__device__ float g_cs0[NS*HS_SLOT];              // c stays fp32
__device__ float g_cs1[NS*HS_SLOT];
__device__ float g_preds[NPRED][NS*PRED_SLOT];              // fp32 (output path)
__device__ __align__(16) uint16_t g_preds16[NPRED][NS*PRED_SLOT];  // f16 bits
__device__ __align__(16) uint16_t g_in16[NS*PRED_SLOT];
__device__ __align__(16) uint16_t g_w16_ih0[4096*FF];
__device__ __align__(16) uint16_t g_w16_hh0[4096*HH];
__device__ __align__(16) uint16_t g_w16_ih1[4096*HH];
__device__ __align__(16) uint16_t g_w16_hh1[4096*HH];
__device__ __align__(16) uint16_t g_w16_lin[FF*HH];
__device__ float g_gates0[BB * 4096];   // bias-preloaded gate accumulators
__device__ float g_gates1[BB * 4096];
__device__ float g_bsum0[4096];         // bih+bhh per gate-col (re-arm source)
__device__ float g_bsum1[4096];
__device__ int   g_cntA[64];            // per-jblk split arrival counters, layer0
__device__ int   g_cntB[64];            // layer1
__device__ int   g_bar;                 // persistent-kernel grid barrier
__device__ int   g_gen;

// ---------------- helpers ----------------
__device__ __forceinline__ uint32_t pack_h2(float lo, float hi) {
    uint32_t r;
    asm("cvt.rn.f16x2.f32 %0, %1, %2;" : "=r"(r) : "f"(hi), "f"(lo));
    return r;
}

__device__ __forceinline__ uint16_t f2h1(float x) {
    uint16_t r;
    asm("cvt.rn.f16.f32 %0, %1;" : "=h"(r) : "f"(x));
    return r;
}

__device__ __forceinline__ float h2f(uint16_t b) {
    float f;
    asm("{ .reg .b16 h; mov.b16 h, %1; cvt.f32.f16 %0, h; }" : "=f"(f) : "h"(b));
    return f;
}

__device__ __forceinline__ void mma16(float* c, uint32_t a0, uint32_t a1, uint32_t a2,
                                      uint32_t a3, uint32_t b0, uint32_t b1) {
    asm volatile(
        "mma.sync.aligned.m16n8k16.row.col.f32.f16.f16.f32 "
        "{%0,%1,%2,%3},{%4,%5,%6,%7},{%8,%9},{%0,%1,%2,%3};\n"
        : "+f"(c[0]), "+f"(c[1]), "+f"(c[2]), "+f"(c[3])
        : "r"(a0), "r"(a1), "r"(a2), "r"(a3), "r"(b0), "r"(b1));
}

__device__ __forceinline__ float sigf(float x) { return 1.f / (1.f + __expf(-x)); }

__device__ __forceinline__ void pick_src16(int c, int nx, int shift,
    const uint16_t* Ax, int Kx, const uint16_t* Ah,
    const uint16_t* Wih, const uint16_t* Whh,
    const uint16_t*& A, const uint16_t*& W, int& K, int& k0)
{
    if (c < nx) { A = Ax; W = Wih; K = Kx; k0 = c << shift; }
    else        { A = Ah; W = Whh; K = HH; k0 = (c - nx) << shift; }
}

// grid-wide barrier for the persistent chain kernel (all NCTA CTAs resident)
__device__ __forceinline__ void grid_barrier(int tid) {
    __syncthreads();
    if (tid == 0) {
        __threadfence();
        volatile int* genp = &g_gen;
        int g = *genp;
        if (atomicAdd(&g_bar, 1) == NCTA - 1) {
            g_bar = 0;
            __threadfence();
            atomicAdd(&g_gen, 1);
        } else {
            while (*genp == g) __nanosleep(64);
        }
        __threadfence();
    }
    __syncthreads();
}

// =====================================================================
// Fused chain cell phase: BM=128 x BN=64 GEMM (f16, proven tile) with
// split-K strided by nsplit; last-arriving split CTA per jblk applies the
// LSTM epilogue for its 16 units and re-arms the gate buffer. No grid
// barrier inside — caller barriers once per phase.
// =====================================================================
__device__ __forceinline__ void chain_cell(
    const uint16_t* __restrict__ Ax, int Kx,
    const uint16_t* __restrict__ Ah,
    const uint16_t* __restrict__ Wih, const uint16_t* __restrict__ Whh,
    float* __restrict__ gates, const float* __restrict__ bsum,
    int* __restrict__ cnt, int nsplit,
    const float* __restrict__ cprev,
    uint16_t* __restrict__ hout, float* __restrict__ cout,
    int jblk, int split, uint32_t* sA, uint32_t* sB, int tid)
{
    const int warp = tid >> 5, lane = tid & 31;
    const int gid  = lane >> 2, tig = lane & 3;
    const int wm   = warp * 16;
    const int j0   = jblk * 16;
    const int nx   = Kx >> 6;
    const int nch  = nx + 16;          // + HH/64

    float acc[8][4];
    #pragma unroll
    for (int i = 0; i < 8; i++)
        #pragma unroll
        for (int q = 0; q < 4; q++) acc[i][q] = 0.f;

    uint4 pA[4], pB[2];
    auto issue = [&](int c) {
        const uint16_t *A, *W; int K, k0;
        pick_src16(c, nx, 6, Ax, Kx, Ah, Wih, Whh, A, W, K, k0);
        #pragma unroll
        for (int i = 0; i < 4; i++) {
            int q = tid + (i << 8);
            int r = q >> 3, c8 = q & 7;
            pA[i] = *(const uint4*)(A + (size_t)r * K + k0 + c8 * 8);
        }
        #pragma unroll
        for (int i = 0; i < 2; i++) {
            int q = tid + (i << 8);
            int r = q >> 3, c8 = q & 7;
            int wr = (r >> 4) * HH + j0 + (r & 15);
            pB[i] = *(const uint4*)(W + (size_t)wr * K + k0 + c8 * 8);
        }
    };

    issue(split);
    for (int c = split; c < nch; c += nsplit) {
        #pragma unroll
        for (int i = 0; i < 4; i++) {
            int q = tid + (i << 8);
            int r = q >> 3, c8 = q & 7;
            *(uint4*)(sA + r * 36 + c8 * 4) = pA[i];
        }
        #pragma unroll
        for (int i = 0; i < 2; i++) {
            int q = tid + (i << 8);
            int r = q >> 3, c8 = q & 7;
            *(uint4*)(sB + r * 36 + c8 * 4) = pB[i];
        }
        __syncthreads();
        if (c + nsplit < nch) issue(c + nsplit);
        const int mr = wm + gid;
        #pragma unroll
        for (int ks = 0; ks < 4; ks++) {
            uint32_t a0 = sA[mr * 36 + ks * 8 + tig];
            uint32_t a1 = sA[(mr + 8) * 36 + ks * 8 + tig];
            uint32_t a2 = sA[mr * 36 + ks * 8 + 4 + tig];
            uint32_t a3 = sA[(mr + 8) * 36 + ks * 8 + 4 + tig];
            #pragma unroll
            for (int in = 0; in < 8; in++) {
                int nr = in * 8 + gid;
                uint32_t b0 = sB[nr * 36 + ks * 8 + tig];
                uint32_t b1 = sB[nr * 36 + ks * 8 + 4 + tig];
                mma16(acc[in], a0, a1, a2, a3, b0, b1);
            }
        }
        __syncthreads();
    }

    // accumulate partial gates into bias-preloaded buffer
    {
        const int m = wm + gid;
        #pragma unroll
        for (int in = 0; in < 8; in++) {
            int nl = in * 8 + 2 * tig;
            int gc = (nl >> 4) * HH + j0 + (nl & 15);
            atomicAdd(&gates[(size_t)m * 4096 + gc],           acc[in][0]);
            atomicAdd(&gates[(size_t)m * 4096 + gc + 1],       acc[in][1]);
            atomicAdd(&gates[(size_t)(m + 8) * 4096 + gc],     acc[in][2]);
            atomicAdd(&gates[(size_t)(m + 8) * 4096 + gc + 1], acc[in][3]);
        }
    }

    // fused epilogue: last split CTA for this jblk does the LSTM update
    __shared__ int isLast;
    __threadfence();
    __syncthreads();
    if (tid == 0) {
        int old = atomicAdd(&cnt[jblk], 1);
        isLast = (old == nsplit - 1);
    }
    __syncthreads();
    if (isLast) {
        __threadfence();
        #pragma unroll
        for (int e = tid; e < 2048; e += 256) {     // 128 rows x 16 units
            int m = e >> 4, j = e & 15;
            int unit = j0 + j;
            size_t gb = (size_t)m * 4096;
            float gi = __ldcg(&gates[gb + unit]);
            float gf = __ldcg(&gates[gb + HH + unit]);
            float gg = __ldcg(&gates[gb + 2 * HH + unit]);
            float go = __ldcg(&gates[gb + 3 * HH + unit]);
            float c2 = sigf(gf) * cprev[(size_t)m * HH + unit] + sigf(gi) * tanhf(gg);
            cout[(size_t)m * HH + unit] = c2;
            hout[(size_t)m * HH + unit] = f2h1(sigf(go) * tanhf(c2));
            gates[gb + unit]          = bsum[unit];
            gates[gb + HH + unit]     = bsum[HH + unit];
            gates[gb + 2 * HH + unit] = bsum[2 * HH + unit];
            gates[gb + 3 * HH + unit] = bsum[3 * HH + unit];
        }
        if (tid == 0) cnt[jblk] = 0;
    }
}

// =====================================================================
// Persistent pipelined chain: phase p runs GEMM_L1(k) on CTAs 0-127 and
// GEMM_L0(k+1) on CTAs 128-255 concurrently; ONE grid barrier per phase.
// =====================================================================
__global__ __launch_bounds__(256, 2) void lstm_chain_persistent(
    const uint16_t* __restrict__ in16,
    uint16_t* __restrict__ h16_0, uint16_t* __restrict__ h16_1,
    const uint16_t* __restrict__ w_ih0, const uint16_t* __restrict__ w_hh0,
    const uint16_t* __restrict__ w_ih1, const uint16_t* __restrict__ w_hh1,
    float* __restrict__ gates0, float* __restrict__ gates1,
    float* __restrict__ cs0, float* __restrict__ cs1)
{
    __shared__ uint32_t su[128 * 36 + 64 * 36];
    uint32_t* sA = su;
    uint32_t* sB = su + 128 * 36;

    const int tid = threadIdx.x;
    const int bid = blockIdx.x;

    // pre-phase: L0 step 1, all 256 CTAs (4 splits x 64 jblk)
    chain_cell(in16 + (size_t)1 * PRED_SLOT, FF, h16_0,
               w_ih0, w_hh0, gates0, g_bsum0, g_cntA, 4,
               cs0, h16_0 + (size_t)1 * HS_SLOT, cs0 + (size_t)1 * HS_SLOT,
               bid & 63, bid >> 6, sA, sB, tid);
    grid_barrier(tid);

    for (int k = 1; k < NS; k++) {
        if (bid < 128) {
            // layer1 step k (needs h0[k] from previous phase)
            chain_cell(h16_0 + (size_t)k * HS_SLOT, HH,
                       h16_1 + (size_t)(k - 1) * HS_SLOT,
                       w_ih1, w_hh1, gates1, g_bsum1, g_cntB, 2,
                       cs1 + (size_t)(k - 1) * HS_SLOT,
                       h16_1 + (size_t)k * HS_SLOT, cs1 + (size_t)k * HS_SLOT,
                       bid & 63, bid >> 6, sA, sB, tid);
        } else if (k + 1 < NS) {
            // layer0 step k+1 (also only needs h0[k])
            int b = bid - 128;
            chain_cell(in16 + (size_t)(k + 1) * PRED_SLOT, FF,
                       h16_0 + (size_t)k * HS_SLOT,
                       w_ih0, w_hh0, gates0, g_bsum0, g_cntA, 2,
                       cs0 + (size_t)k * HS_SLOT,
                       h16_0 + (size_t)(k + 1) * HS_SLOT,
                       cs0 + (size_t)(k + 1) * HS_SLOT,
                       b & 63, b >> 6, sA, sB, tid);
        }
        grid_barrier(tid);
    }
}

// =====================================================================
// Batched inner cell (f16 bits — PROVEN R11/R12/R16): BM=256 x BN=128.
// grid (32, nk/2), 512 threads.
// =====================================================================
__global__ __launch_bounds__(512) void lstm_big(
    const uint16_t* __restrict__ Ax, int Kx,
    const uint16_t* __restrict__ Ah,
    const uint16_t* __restrict__ Wih, const uint16_t* __restrict__ Whh,
    const float* __restrict__ bih, const float* __restrict__ bhh,
    const float* __restrict__ cprev,
    uint16_t* __restrict__ hout, float* __restrict__ cout)
{
    __shared__ uint32_t su[256 * 20 + 128 * 20];
    __shared__ float sBias[128];
    uint32_t* sA = su;
    uint32_t* sB = su + 256 * 20;

    const int tid  = threadIdx.x;
    const int warp = tid >> 5, lane = tid & 31;
    const int gid  = lane >> 2, tig = lane & 3;
    const int wm   = warp * 16;
    const int j0   = blockIdx.x * 32;
    const size_t rowbase = (size_t)blockIdx.y * 256;
    const int nx = Kx >> 5, C = nx + 32;
    const int lr = tid >> 2;        // 0..127
    const int lc = tid & 3;

    if (tid < 128)
        sBias[tid] = bih[(tid >> 5) * HH + j0 + (tid & 31)]
                   + bhh[(tid >> 5) * HH + j0 + (tid & 31)];

    float acc[16][4];
    #pragma unroll
    for (int i = 0; i < 16; i++)
        #pragma unroll
        for (int q = 0; q < 4; q++) acc[i][q] = 0.f;

    const uint16_t *A, *W; int K, k0;
    pick_src16(0, nx, 5, Ax, Kx, Ah, Wih, Whh, A, W, K, k0);
    const int wr = (lr >> 5) * HH + j0 + (lr & 31);
    uint4 pA0 = *(const uint4*)(A + (rowbase + lr) * (size_t)K + k0 + lc * 8);
    uint4 pA1 = *(const uint4*)(A + (rowbase + lr + 128) * (size_t)K + k0 + lc * 8);
    uint4 pB  = *(const uint4*)(W + (size_t)wr * K + k0 + lc * 8);

    for (int c = 0; c < C; c++) {
        *(uint4*)(sA + lr * 20 + lc * 4)         = pA0;
        *(uint4*)(sA + (lr + 128) * 20 + lc * 4) = pA1;
        *(uint4*)(sB + lr * 20 + lc * 4)         = pB;
        __syncthreads();
        if (c + 1 < C) {
            pick_src16(c + 1, nx, 5, Ax, Kx, Ah, Wih, Whh, A, W, K, k0);
            pA0 = *(const uint4*)(A + (rowbase + lr) * (size_t)K + k0 + lc * 8);
            pA1 = *(const uint4*)(A + (rowbase + lr + 128) * (size_t)K + k0 + lc * 8);
            pB  = *(const uint4*)(W + (size_t)wr * K + k0 + lc * 8);
        }
        const int mr = wm + gid;
        #pragma unroll
        for (int ks = 0; ks < 2; ks++) {
            uint32_t a0 = sA[mr * 20 + ks * 8 + tig];
            uint32_t a1 = sA[(mr + 8) * 20 + ks * 8 + tig];
            uint32_t a2 = sA[mr * 20 + ks * 8 + 4 + tig];
            uint32_t a3 = sA[(mr + 8) * 20 + ks * 8 + 4 + tig];
            #pragma unroll
            for (int in = 0; in < 16; in++) {
                int nr = in * 8 + gid;
                uint32_t b0 = sB[nr * 20 + ks * 8 + tig];
                uint32_t b1 = sB[nr * 20 + ks * 8 + 4 + tig];
                mma16(acc[in], a0, a1, a2, a3, b0, b1);
            }
        }
        __syncthreads();
    }

    // ---- register-local LSTM epilogue ----
    #pragma unroll
    for (int in = 0; in < 4; in++)
        #pragma unroll
        for (int half = 0; half < 2; half++) {
            int q0 = half * 2;
            int u0 = in * 8 + 2 * tig;
            int m  = wm + gid + half * 8;
            size_t off = (rowbase + m) * HH + j0 + u0;
            float2 cp = *(const float2*)(cprev + off);
            float gi0 = acc[in][q0]          + sBias[u0];
            float gf0 = acc[in + 4][q0]      + sBias[32 + u0];
            float gg0 = acc[in + 8][q0]      + sBias[64 + u0];
            float go0 = acc[in + 12][q0]     + sBias[96 + u0];
            float gi1 = acc[in][q0 + 1]      + sBias[u0 + 1];
            float gf1 = acc[in + 4][q0 + 1]  + sBias[32 + u0 + 1];
            float gg1 = acc[in + 8][q0 + 1]  + sBias[64 + u0 + 1];
            float go1 = acc[in + 12][q0 + 1] + sBias[96 + u0 + 1];
            float c2a = sigf(gf0) * cp.x + sigf(gi0) * tanhf(gg0);
            float c2b = sigf(gf1) * cp.y + sigf(gi1) * tanhf(gg1);
            float h2a = sigf(go0) * tanhf(c2a);
            float h2b = sigf(go1) * tanhf(c2b);
            float2 cv; cv.x = c2a; cv.y = c2b;
            *(float2*)(cout + off) = cv;
            *(uint32_t*)(hout + off) = pack_h2(h2a, h2b);
        }
}

// =====================================================================
// Linear (f16 bits — PROVEN): out[rows,128] = A @ W^T + b. grid (2, rows/64).
// =====================================================================
__global__ __launch_bounds__(128) void linear_kernel(
    const uint16_t* __restrict__ A,
    const uint16_t* __restrict__ W,
    const float* __restrict__ bias,
    float* __restrict__ out, uint16_t* __restrict__ out16)
{
    __shared__ uint32_t su[64 * 20 * 2];
    uint32_t* sA = su;
    uint32_t* sB = su + 64 * 20;

    const int tid  = threadIdx.x;
    const int warp = tid >> 5, lane = tid & 31;
    const int gid  = lane >> 2, tig = lane & 3;
    const int wm   = warp * 16;
    const int n0   = blockIdx.x * 64;
    const size_t rowbase = (size_t)blockIdx.y * 64;
    const int lr = tid >> 2;   // 0..31
    const int lc = tid & 3;

    float acc[8][4];
    #pragma unroll
    for (int i = 0; i < 8; i++)
        #pragma unroll
        for (int q = 0; q < 4; q++) acc[i][q] = 0.f;

    for (int k0 = 0; k0 < HH; k0 += 32) {
        *(uint4*)(sA + lr * 20 + lc * 4) =
            *(const uint4*)(A + (rowbase + lr) * (size_t)HH + k0 + lc * 8);
        *(uint4*)(sA + (lr + 32) * 20 + lc * 4) =
            *(const uint4*)(A + (rowbase + lr + 32) * (size_t)HH + k0 + lc * 8);
        *(uint4*)(sB + lr * 20 + lc * 4) =
            *(const uint4*)(W + (size_t)(n0 + lr) * HH + k0 + lc * 8);
        *(uint4*)(sB + (lr + 32) * 20 + lc * 4) =
            *(const uint4*)(W + (size_t)(n0 + lr + 32) * HH + k0 + lc * 8);
        __syncthreads();
        const int mr = wm + gid;
        #pragma unroll
        for (int ks = 0; ks < 2; ks++) {
            uint32_t a0 = sA[mr * 20 + ks * 8 + tig];
            uint32_t a1 = sA[(mr + 8) * 20 + ks * 8 + tig];
            uint32_t a2 = sA[mr * 20 + ks * 8 + 4 + tig];
            uint32_t a3 = sA[(mr + 8) * 20 + ks * 8 + 4 + tig];
            #pragma unroll
            for (int in = 0; in < 8; in++) {
                int nr = in * 8 + gid;
                uint32_t b0 = sB[nr * 20 + ks * 8 + tig];
                uint32_t b1 = sB[nr * 20 + ks * 8 + 4 + tig];
                mma16(acc[in], a0, a1, a2, a3, b0, b1);
            }
        }
        __syncthreads();
    }

    #pragma unroll
    for (int in = 0; in < 8; in++)
        #pragma unroll
        for (int half = 0; half < 2; half++) {
            int q0 = half * 2;
            int n  = n0 + in * 8 + 2 * tig;
            int m  = wm + gid + half * 8;
            size_t row = rowbase + m;
            float va = acc[in][q0]     + bias[n];
            float vb = acc[in][q0 + 1] + bias[n + 1];
            float2 v; v.x = va; v.y = vb;
            *(float2*)(out + row * FF + n) = v;
            *(uint32_t*)(out16 + row * FF + n) = pack_h2(va, vb);
        }
}

// ---------------- fp32 -> f16-bits convert (paired) ----------------
__global__ void f2h_kernel(const float* __restrict__ src, uint32_t* __restrict__ dst,
                           int npairs) {
    for (int i = blockIdx.x * blockDim.x + threadIdx.x; i < npairs;
         i += gridDim.x * blockDim.x)
        dst[i] = pack_h2(src[2 * i], src[2 * i + 1]);
}

// ---------------- init: seed states, bias sums, gate buffers, barriers ----------------
__global__ void init_states(const float* __restrict__ h0, const float* __restrict__ c0,
    const float* __restrict__ bih0, const float* __restrict__ bhh0,
    const float* __restrict__ bih1, const float* __restrict__ bhh1)
{
    int i = blockIdx.x * blockDim.x + threadIdx.x;   // grid 2048x256
    if (i < HS_SLOT) {
        g_h16_0[0][i] = f2h1(h0[i]);
        g_h16_1[0][i] = f2h1(h0[HS_SLOT + i]);
        g_cs0[i] = c0[i];
        g_cs1[i] = c0[HS_SLOT + i];
    }
    if (i < BB * 4096) {
        int col = i & 4095;
        g_gates0[i] = bih0[col] + bhh0[col];
        g_gates1[i] = bih1[col] + bhh1[col];
    }
    if (i < 4096) {
        g_bsum0[i] = bih0[i] + bhh0[i];
        g_bsum1[i] = bih1[i] + bhh1[i];
    }
    if (i < 64) { g_cntA[i] = 0; g_cntB[i] = 0; }
    if (i == 0) { g_bar = 0; g_gen = 0; }
}

// ---------------- output assembly ----------------
__global__ void assemble(const float* __restrict__ inMusic, float* __restrict__ out) {
    const size_t OUTM = (size_t)NS * BB * FF * NPRED;
    const size_t HFO  = OUTM;
    const size_t CFO  = HFO + 2 * (size_t)HS_SLOT;
    const size_t NSE  = CFO + 2 * (size_t)HS_SLOT;
    const size_t TOT  = NSE + PRED_SLOT;
    for (size_t idx = blockIdx.x * (size_t)blockDim.x + threadIdx.x; idx < TOT;
         idx += (size_t)gridDim.x * blockDim.x) {
        float v;
        if (idx < OUTM) {
            int n = (int)(idx & 7);
            int f = (int)((idx >> 3) & 127);
            int b = (int)((idx >> 10) & 127);
            int r = (int)(idx >> 17);
            if (r < NPRED && n >= r)
                v = inMusic[((size_t)r * BB + b) * FF + f];
            else if (r >= 2 * n + 2)
                v = g_preds[n][(size_t)(r - n - 1) * PRED_SLOT + b * FF + f];
            else
                v = 0.f;
        } else if (idx < CFO) {
            size_t i = idx - HFO;
            size_t rest = i & (HS_SLOT - 1);
            v = (i >= HS_SLOT) ? h2f(g_h16_1[0][95 * (size_t)HS_SLOT + rest])
                               : h2f(g_h16_0[0][95 * (size_t)HS_SLOT + rest]);
        } else if (idx < NSE) {
            size_t i = idx - CFO;
            size_t rest = i & (HS_SLOT - 1);
            v = (i >= HS_SLOT) ? g_cs1[95 * (size_t)HS_SLOT + rest]
                               : g_cs0[95 * (size_t)HS_SLOT + rest];
        } else {
            v = g_preds[0][95 * (size_t)PRED_SLOT + (idx - NSE)];
        }
        out[idx] = v;
    }
}

// ---------------- host orchestration ----------------
extern "C" void kernel_launch(void* const* d_in, const int* in_sizes, int n_in,
                              void* d_out, int out_size) {
    const float* inMusic = (const float*)d_in[0];
    const float* h0   = (const float*)d_in[1];
    const float* c0   = (const float*)d_in[2];
    const float* Wih0 = (const float*)d_in[3];
    const float* Whh0 = (const float*)d_in[4];
    const float* bih0 = (const float*)d_in[5];
    const float* bhh0 = (const float*)d_in[6];
    const float* Wih1 = (const float*)d_in[7];
    const float* Whh1 = (const float*)d_in[8];
    const float* bih1 = (const float*)d_in[9];
    const float* bhh1 = (const float*)d_in[10];
    const float* Wlin = (const float*)d_in[11];
    const float* blin = (const float*)d_in[12];
    float* out = (float*)d_out;

    float *cs0, *cs1, *preds, *gates0, *gates1;
    uint16_t *h16_0, *h16_1, *preds16, *in16, *w_ih0, *w_hh0, *w_ih1, *w_hh1, *w_lin;
    cudaGetSymbolAddress((void**)&h16_0, g_h16_0);
    cudaGetSymbolAddress((void**)&h16_1, g_h16_1);
    cudaGetSymbolAddress((void**)&cs0, g_cs0);
    cudaGetSymbolAddress((void**)&cs1, g_cs1);
    cudaGetSymbolAddress((void**)&preds, g_preds);
    cudaGetSymbolAddress((void**)&preds16, g_preds16);
    cudaGetSymbolAddress((void**)&in16, g_in16);
    cudaGetSymbolAddress((void**)&w_ih0, g_w16_ih0);
    cudaGetSymbolAddress((void**)&w_hh0, g_w16_hh0);
    cudaGetSymbolAddress((void**)&w_ih1, g_w16_ih1);
    cudaGetSymbolAddress((void**)&w_hh1, g_w16_hh1);
    cudaGetSymbolAddress((void**)&w_lin, g_w16_lin);
    cudaGetSymbolAddress((void**)&gates0, g_gates0);
    cudaGetSymbolAddress((void**)&gates1, g_gates1);
    const size_t BUF = (size_t)NS * HS_SLOT;

    // --- conversions to f16 bits (deterministic each call) ---
    f2h_kernel<<<256, 256>>>(Wih0, (uint32_t*)w_ih0, 4096 * FF / 2);
    f2h_kernel<<<2048, 256>>>(Whh0, (uint32_t*)w_hh0, 4096 * HH / 2);
    f2h_kernel<<<2048, 256>>>(Wih1, (uint32_t*)w_ih1, 4096 * HH / 2);
    f2h_kernel<<<2048, 256>>>(Whh1, (uint32_t*)w_hh1, 4096 * HH / 2);
    f2h_kernel<<<256, 256>>>(Wlin, (uint32_t*)w_lin, FF * HH / 2);
    f2h_kernel<<<1024, 256>>>(inMusic, (uint32_t*)in16, NS * PRED_SLOT / 2);
    init_states<<<2048, 256>>>(h0, c0, bih0, bhh0, bih1, bhh1);

    // --- entire chain, pipelined, ONE launch, 1 barrier/step ---
    lstm_chain_persistent<<<NCTA, 256>>>(
        in16, h16_0, h16_1, w_ih0, w_hh0, w_ih1, w_hh1,
        gates0, gates1, cs0, cs1);

    // --- pred0 for k = 1..95 ---
    linear_kernel<<<dim3(2, 95 * 2), 128>>>(h16_1 + HS_SLOT, w_lin, blin,
                                            preds + PRED_SLOT, preds16 + PRED_SLOT);

    // --- closed-loop prediction steps, batched across active k ---
    for (int n = 1; n < NPRED; n++) {
        int k0 = n + 1;
        int nk = 94 - 2 * n;                 // even: 92..80
        int src = (n - 1) & 1, dst = n & 1;
        size_t off = (size_t)k0 * HS_SLOT;
        lstm_big<<<dim3(32, nk / 2), 512>>>(
            preds16 + (size_t)(n - 1) * NS * PRED_SLOT + (size_t)k0 * PRED_SLOT, FF,
            h16_0 + src * BUF + off, w_ih0, w_hh0, bih0, bhh0,
            cs0 + off, h16_0 + dst * BUF + off, cs0 + off);
        lstm_big<<<dim3(32, nk / 2), 512>>>(
            h16_0 + dst * BUF + off, HH,
            h16_1 + src * BUF + off, w_ih1, w_hh1, bih1, bhh1,
            cs1 + off, h16_1 + dst * BUF + off, cs1 + off);
        linear_kernel<<<dim3(2, nk * 2), 128>>>(
            h16_1 + dst * BUF + off, w_lin, blin,
            preds + (size_t)n * NS * PRED_SLOT + (size_t)k0 * PRED_SLOT,
            preds16 + (size_t)n * NS * PRED_SLOT + (size_t)k0 * PRED_SLOT);
    }

    assemble<<<4096, 256>>>(inMusic, out);
    (void)in_sizes; (void)n_in; (void)out_size;
}